// round 11
// baseline (speedup 1.0000x reference)
#include <cuda_runtime.h>
#include <cuda_fp16.h>
#include <mma.h>
#include <math.h>

using namespace nvcuda;

#define NNODES_MAX 100000
#define NEDGES_MAX 1600000
#define IN_DIM 128
#define HID 64
#define KTOT 320   // IN_DIM + 3*HID
#define NCOLS 256  // 4 gates * HID
#define KC 32
#define NCHUNK 10  // KTOT / KC
#define NPB 64
#define SCAN_BS 256
#define MAX_SBLK 512

// smem layout (bytes), GEMM phase:
//   WH[buf] @ buf*32768        (32x256 half = 16384)
//   WL[buf] @ buf*32768+16384
//   AH[buf] @ 65536+buf*10240  (64x40 half = 5120)
//   AL[buf] @ 65536+buf*10240+5120
// epilogue phase (overlaps GEMM buffers, used after final sync):
//   pre @ 0      (64 x 264 f32 = 67584)
//   Hs  @ 67584  (64x64 f32 = 16384)
//   Wls @ 83968  (16384)
#define SMEM_BYTES 100352
#define A_LD 40    // halves per A row (32 + 8 pad)
#define PRE_LD 264

// ---------------- scratch (static device globals; no allocation) ----------------
__device__ __align__(16) float g_deg [NNODES_MAX];
__device__ __align__(16) int   g_cnt [NNODES_MAX];
__device__ __align__(16) int   g_off [NNODES_MAX];
__device__ __align__(16) int   g_cur [NNODES_MAX];
__device__ __align__(16) int   g_bsum[MAX_SBLK];
__device__ __align__(16) long long g_pay[NEDGES_MAX];   // {lw(f32)<<32 | src}
__device__ __align__(16) float g_Tx1 [NNODES_MAX * HID];
__device__ __align__(16) float g_Tx2 [NNODES_MAX * HID];
__device__ __align__(16) __half g_Wph[KTOT * NCOLS];    // W fp16 hi, [k][n]
__device__ __align__(16) __half g_Wpl[KTOT * NCOLS];    // W fp16 lo
__device__ __align__(16) float g_biasp[NCOLS];

// ---------------- helpers ----------------
__device__ __forceinline__ float sigf(float v) { return 1.0f / (1.0f + expf(-v)); }

__device__ __forceinline__ void cp16(void* smem, const void* gmem) {
    unsigned sa = (unsigned)__cvta_generic_to_shared(smem);
    asm volatile("cp.async.cg.shared.global [%0], [%1], 16;" :: "r"(sa), "l"(gmem));
}
#define CP_COMMIT() asm volatile("cp.async.commit_group;" ::: "memory")
#define CP_WAIT0()  asm volatile("cp.async.wait_group 0;"  ::: "memory")

// ---------------- zero scratch + counters ----------------
__global__ void k_zero(int N) {
    int i = blockIdx.x * blockDim.x + threadIdx.x;
    if (i < N) { g_deg[i] = 0.0f; g_cnt[i] = 0; }
}

// ---------------- prep (deg + hist) fused with weight pack (fp16 split) ----------------
__global__ void k_preppack(const int* __restrict__ src, const int* __restrict__ dst,
                           const float* __restrict__ ew, int E, int eb,
                           const float* __restrict__ Wx, const float* __restrict__ bg,
                           const float* __restrict__ theta, const float* __restrict__ convb) {
    int b = blockIdx.x;
    if (b < eb) {
        int e = b * 256 + threadIdx.x;
        if (e >= E) return;
        int s = src[e], d = dst[e];
        float w = (s == d) ? 0.0f : ew[e];
        if (w != 0.0f) atomicAdd(&g_deg[s], w);
        atomicAdd(&g_cnt[d], 1);
    } else {
        int idx = (b - eb) * 256 + threadIdx.x;
        if (idx >= KTOT * NCOLS) return;
        int k = idx / NCOLS, j = idx % NCOLS;
        int g = j >> 6, o = j & 63;
        float v;
        if (k < IN_DIM) {
            v = Wx[(g * IN_DIM + k) * HID + o];
        } else {
            int kk = k - IN_DIM;
            v = theta[((g * 3 + kk / HID) * HID + (kk % HID)) * HID + o];
        }
        __half hi = __float2half(v);
        __half lo = __float2half(v - __half2float(hi));
        g_Wph[idx] = hi;
        g_Wpl[idx] = lo;
        if (idx < NCOLS) g_biasp[idx] = bg[idx] + convb[idx];
    }
}

// ---------------- deterministic exclusive scan (node-ordered CSR) ----------------
__global__ void k_scan1(int N) {
    __shared__ int sm[SCAN_BS];
    int t = threadIdx.x;
    int i = blockIdx.x * SCAN_BS + t;
    int v = (i < N) ? g_cnt[i] : 0;
    sm[t] = v; __syncthreads();
    #pragma unroll
    for (int d = 1; d < SCAN_BS; d <<= 1) {
        int u = (t >= d) ? sm[t - d] : 0;
        __syncthreads();
        sm[t] += u;
        __syncthreads();
    }
    if (i < N) g_off[i] = sm[t] - v;
    if (t == SCAN_BS - 1) g_bsum[blockIdx.x] = sm[t];
}
__global__ void k_scan2(int nb) {
    __shared__ int sm[MAX_SBLK];
    int t = threadIdx.x;
    int v = (t < nb) ? g_bsum[t] : 0;
    sm[t] = v; __syncthreads();
    #pragma unroll
    for (int d = 1; d < MAX_SBLK; d <<= 1) {
        int u = (t >= d) ? sm[t - d] : 0;
        __syncthreads();
        sm[t] += u;
        __syncthreads();
    }
    if (t < nb) g_bsum[t] = sm[t] - v;
}
__global__ void k_scan3(int N) {
    int i = blockIdx.x * SCAN_BS + threadIdx.x;
    if (i >= N) return;
    int o = g_off[i] + g_bsum[blockIdx.x];
    g_off[i] = o;
    g_cur[i] = o;
}

// ---------------- fill CSR payload {src, lap_w} ----------------
__global__ void k_fill(const int* __restrict__ src, const int* __restrict__ dst,
                       const float* __restrict__ ew, int E) {
    int e = blockIdx.x * blockDim.x + threadIdx.x;
    if (e >= E) return;
    int s = src[e], d = dst[e];
    float w  = (s == d) ? 0.0f : ew[e];
    float ds = g_deg[s], dd = g_deg[d];
    float is = (ds > 0.0f) ? rsqrtf(ds) : 0.0f;
    float id = (dd > 0.0f) ? rsqrtf(dd) : 0.0f;
    float lw = -is * w * id;
    int pos = atomicAdd(&g_cur[d], 1);
    g_pay[pos] = ((long long)(unsigned long long)__float_as_uint(lw) << 32)
                 | (unsigned)s;
}

// ---------------- aggregate: out[n] = sum_j lw_j * z[src_j]  (register acc, MLP=8) ----------------
template <int TX2>
__global__ __launch_bounds__(256) void k_agg(const float4* __restrict__ z,
                                             const float4* __restrict__ hsub,
                                             float4* __restrict__ outb,
                                             int N) {
    int gid = blockIdx.x * blockDim.x + threadIdx.x;
    int n = gid >> 4;
    if (n >= N) return;
    int c = gid & 15;
    int j   = g_off[n];
    int end = j + g_cnt[n];

    float4 acc = make_float4(0.f, 0.f, 0.f, 0.f);
    for (; j + 7 < end; j += 8) {
        long long pp[8];
        #pragma unroll
        for (int u = 0; u < 8; ++u) pp[u] = g_pay[j + u];
        float4 vv[8];
        float  ll[8];
        #pragma unroll
        for (int u = 0; u < 8; ++u) {
            int s = (int)(pp[u] & 0xffffffffLL);
            ll[u] = __uint_as_float((unsigned)((unsigned long long)pp[u] >> 32));
            vv[u] = z[(long)s * 16 + c];
        }
        #pragma unroll
        for (int u = 0; u < 8; ++u) {
            acc.x = fmaf(ll[u], vv[u].x, acc.x);
            acc.y = fmaf(ll[u], vv[u].y, acc.y);
            acc.z = fmaf(ll[u], vv[u].z, acc.z);
            acc.w = fmaf(ll[u], vv[u].w, acc.w);
        }
    }
    for (; j < end; ++j) {
        long long p0 = g_pay[j];
        int   s0 = (int)(p0 & 0xffffffffLL);
        float l0 = __uint_as_float((unsigned)((unsigned long long)p0 >> 32));
        float4 v0 = z[(long)s0 * 16 + c];
        acc.x = fmaf(l0, v0.x, acc.x); acc.y = fmaf(l0, v0.y, acc.y);
        acc.z = fmaf(l0, v0.z, acc.z); acc.w = fmaf(l0, v0.w, acc.w);
    }
    if (TX2) {
        float4 hv = hsub[(long)n * 16 + c];
        acc.x = 2.0f * acc.x - hv.x; acc.y = 2.0f * acc.y - hv.y;
        acc.z = 2.0f * acc.z - hv.z; acc.w = 2.0f * acc.w - hv.w;
    }
    outb[(long)n * 16 + c] = acc;
}

// ---------------- fused GEMM via wmma (split-fp16 3-pass) + gates + relu@Wl ----------------
__global__ __launch_bounds__(256, 2) void k_fused(
    const float* __restrict__ x, const float* __restrict__ h,
    const float* __restrict__ tx1, const float* __restrict__ tx2,
    const float* __restrict__ c, const float* __restrict__ Wl,
    const float* __restrict__ bl, float* __restrict__ out, int N) {

    extern __shared__ __align__(16) char smem[];
    float* smf = (float*)smem;

    const int tid = threadIdx.x;
    const int wid = tid >> 5;
    const int nb = blockIdx.x * NPB;

    // wmma warp mapping: 4 m-tiles x 2 n-halves
    const int mt    = wid >> 1;          // 0..3 (16 nodes each)
    const int nbase = (wid & 1) * 128;   // 0 or 128

    // X loader mapping: node xn, 8-col group xq
    const int xn  = tid >> 2;
    const int xq  = (tid & 3) * 8;
    const int gxn = nb + xn;

    wmma::fragment<wmma::accumulator, 16, 16, 16, float> acc[8];
    #pragma unroll
    for (int t = 0; t < 8; ++t) wmma::fill_fragment(acc[t], 0.0f);

    auto wh_buf = [&](int buf) { return (__half*)(smem + buf * 32768); };
    auto wl_buf = [&](int buf) { return (__half*)(smem + buf * 32768 + 16384); };
    auto ah_buf = [&](int buf) { return (__half*)(smem + 65536 + buf * 10240); };
    auto al_buf = [&](int buf) { return (__half*)(smem + 65536 + buf * 10240 + 5120); };

    auto load_x = [&](int kc, float4& a, float4& b) {
        const float* sp; int ld, col;
        if (kc < 4)      { sp = x;   ld = IN_DIM; col = kc * KC; }
        else if (kc < 6) { sp = h;   ld = HID;    col = (kc - 4) * KC; }
        else if (kc < 8) { sp = tx1; ld = HID;    col = (kc - 6) * KC; }
        else             { sp = tx2; ld = HID;    col = (kc - 8) * KC; }
        if (gxn < N) {
            const float* base = sp + (long)gxn * ld + col + xq;
            a = *reinterpret_cast<const float4*>(base);
            b = *reinterpret_cast<const float4*>(base + 4);
        } else {
            a = make_float4(0.f, 0.f, 0.f, 0.f);
            b = a;
        }
    };
    auto store_x = [&](int buf, float4 a, float4 b) {
        __half hh[8], ll[8];
        const float v[8] = {a.x, a.y, a.z, a.w, b.x, b.y, b.z, b.w};
        #pragma unroll
        for (int u = 0; u < 8; ++u) {
            __half hi = __float2half(v[u]);
            hh[u] = hi;
            ll[u] = __float2half(v[u] - __half2float(hi));
        }
        // row stride = 40 halves = 80B (16B-aligned); col offset xq*2 in {0,16,32,48}
        *reinterpret_cast<uint4*>((char*)ah_buf(buf) + xn * 80 + xq * 2)
            = *reinterpret_cast<const uint4*>(hh);
        *reinterpret_cast<uint4*>((char*)al_buf(buf) + xn * 80 + xq * 2)
            = *reinterpret_cast<const uint4*>(ll);
    };
    auto issue_w = [&](int kc, int buf) {
        const char* sh = (const char*)(g_Wph + kc * KC * NCOLS);
        const char* sl = (const char*)(g_Wpl + kc * KC * NCOLS);
        char* dh = (char*)wh_buf(buf);
        char* dl = (char*)wl_buf(buf);
        #pragma unroll
        for (int r = 0; r < 4; ++r) {
            cp16(dh + (tid + r * 256) * 16, sh + (tid + r * 256) * 16);
            cp16(dl + (tid + r * 256) * 16, sl + (tid + r * 256) * 16);
        }
        CP_COMMIT();
    };

    issue_w(0, 0);
    {
        float4 a, b; load_x(0, a, b);
        store_x(0, a, b);
    }
    CP_WAIT0();
    __syncthreads();

    for (int kc = 0; kc < NCHUNK; ++kc) {
        const int cur = kc & 1;
        float4 xa, xb;
        if (kc < NCHUNK - 1) {
            issue_w(kc + 1, cur ^ 1);
            load_x(kc + 1, xa, xb);
        }
        {
            const __half* AH = ah_buf(cur);
            const __half* AL = al_buf(cur);
            const __half* WH = wh_buf(cur);
            const __half* WL = wl_buf(cur);
            #pragma unroll
            for (int kt = 0; kt < KC; kt += 16) {
                wmma::fragment<wmma::matrix_a, 16, 16, 16, __half, wmma::row_major> a_h, a_l;
                wmma::load_matrix_sync(a_h, AH + mt * 16 * A_LD + kt, A_LD);
                wmma::load_matrix_sync(a_l, AL + mt * 16 * A_LD + kt, A_LD);
                #pragma unroll
                for (int nt = 0; nt < 8; ++nt) {
                    const int col = nbase + nt * 16;
                    wmma::fragment<wmma::matrix_b, 16, 16, 16, __half, wmma::row_major> b_h, b_l;
                    wmma::load_matrix_sync(b_h, WH + kt * NCOLS + col, NCOLS);
                    wmma::load_matrix_sync(b_l, WL + kt * NCOLS + col, NCOLS);
                    wmma::mma_sync(acc[nt], a_h, b_h, acc[nt]);
                    wmma::mma_sync(acc[nt], a_l, b_h, acc[nt]);
                    wmma::mma_sync(acc[nt], a_h, b_l, acc[nt]);
                }
            }
        }
        if (kc < NCHUNK - 1)
            store_x(cur ^ 1, xa, xb);
        CP_WAIT0();
        __syncthreads();
    }

    // ---- store accumulators to smem pre[64][264] (overlaps dead GEMM buffers) ----
    float* pre = smf;
    #pragma unroll
    for (int nt = 0; nt < 8; ++nt)
        wmma::store_matrix_sync(pre + mt * 16 * PRE_LD + nbase + nt * 16,
                                acc[nt], PRE_LD, wmma::mem_row_major);
    __syncthreads();

    // ---- gates + h0/c0 + relu(h0)@Wl + bl ----
    float* Hs  = smf + 16896;   // 67584 B
    float* Wls = smf + 20992;   // 83968 B

    const int p  = tid & 31;
    const int ty = tid >> 5;

    #pragma unroll
    for (int i = 0; i < 8; ++i) {
        int nl = ty + 8 * i;
        int n = nb + nl;
        float r0 = 0.0f, r1 = 0.0f;
        if (n < N) {
            float2 pi = *reinterpret_cast<const float2*>(pre + nl * PRE_LD + 0 * 64 + 2 * p);
            float2 pf = *reinterpret_cast<const float2*>(pre + nl * PRE_LD + 1 * 64 + 2 * p);
            float2 pt = *reinterpret_cast<const float2*>(pre + nl * PRE_LD + 2 * 64 + 2 * p);
            float2 po = *reinterpret_cast<const float2*>(pre + nl * PRE_LD + 3 * 64 + 2 * p);
            float2 bi = *reinterpret_cast<const float2*>(g_biasp + 0 * 64 + 2 * p);
            float2 bf = *reinterpret_cast<const float2*>(g_biasp + 1 * 64 + 2 * p);
            float2 bt = *reinterpret_cast<const float2*>(g_biasp + 2 * 64 + 2 * p);
            float2 bo = *reinterpret_cast<const float2*>(g_biasp + 3 * 64 + 2 * p);
            float2 cold = *reinterpret_cast<const float2*>(c + (long)n * HID + 2 * p);
            float ig0 = sigf(pi.x + bi.x), ig1 = sigf(pi.y + bi.y);
            float fg0 = sigf(pf.x + bf.x), fg1 = sigf(pf.y + bf.y);
            float tg0 = tanhf(pt.x + bt.x), tg1 = tanhf(pt.y + bt.y);
            float og0 = sigf(po.x + bo.x), og1 = sigf(po.y + bo.y);
            float c00 = fg0 * cold.x + ig0 * tg0;
            float c01 = fg1 * cold.y + ig1 * tg1;
            float h00 = og0 * tanhf(c00);
            float h01 = og1 * tanhf(c01);
            *reinterpret_cast<float2*>(out + (long)N * HID + (long)n * HID + 2 * p)
                = make_float2(h00, h01);
            *reinterpret_cast<float2*>(out + 2L * N * HID + (long)n * HID + 2 * p)
                = make_float2(c00, c01);
            r0 = fmaxf(h00, 0.0f);
            r1 = fmaxf(h01, 0.0f);
        }
        Hs[nl * 64 + 2 * p]     = r0;
        Hs[nl * 64 + 2 * p + 1] = r1;
    }
    {
        float4* wl4 = reinterpret_cast<float4*>(Wls);
        const float4* wlg = reinterpret_cast<const float4*>(Wl);
        #pragma unroll
        for (int r = 0; r < 4; ++r) wl4[tid + r * 256] = wlg[tid + r * 256];
    }
    __syncthreads();

    float o0[8], o1[8];
    {
        float b0 = bl[2 * p], b1 = bl[2 * p + 1];
        #pragma unroll
        for (int i = 0; i < 8; ++i) { o0[i] = b0; o1[i] = b1; }
    }
    for (int k = 0; k < 64; ++k) {
        float2 w = *reinterpret_cast<const float2*>(Wls + k * 64 + 2 * p);
        #pragma unroll
        for (int i = 0; i < 8; ++i) {
            float a = Hs[(ty + 8 * i) * 64 + k];
            o0[i] = fmaf(a, w.x, o0[i]);
            o1[i] = fmaf(a, w.y, o1[i]);
        }
    }
    #pragma unroll
    for (int i = 0; i < 8; ++i) {
        int n = nb + ty + 8 * i;
        if (n < N)
            *reinterpret_cast<float2*>(out + (long)n * HID + 2 * p) = make_float2(o0[i], o1[i]);
    }
}

// ---------------- launch ----------------
extern "C" void kernel_launch(void* const* d_in, const int* in_sizes, int n_in,
                              void* d_out, int out_size) {
    const float* x   = (const float*)d_in[0];
    const int*   ei  = (const int*)d_in[1];
    const float* ew  = (const float*)d_in[2];
    const float* h   = (const float*)d_in[3];
    const float* c   = (const float*)d_in[4];
    const float* Wx  = (const float*)d_in[5];
    const float* bg  = (const float*)d_in[6];
    const float* th  = (const float*)d_in[7];
    const float* cb  = (const float*)d_in[8];
    const float* Wl  = (const float*)d_in[9];
    const float* bl  = (const float*)d_in[10];
    float* out = (float*)d_out;

    const int N = in_sizes[0] / IN_DIM;
    const int E = in_sizes[1] / 2;
    const int* src = ei;
    const int* dst = ei + E;

    void *p_tx1, *p_tx2;
    cudaGetSymbolAddress(&p_tx1, g_Tx1);
    cudaGetSymbolAddress(&p_tx2, g_Tx2);

    static int smem_set = 0;
    if (!smem_set) {
        cudaFuncSetAttribute(k_fused, cudaFuncAttributeMaxDynamicSharedMemorySize,
                             SMEM_BYTES);
        smem_set = 1;
    }

    const int eb = (E + 255) / 256;
    const int pb = (KTOT * NCOLS + 255) / 256;
    const int nb = (N + SCAN_BS - 1) / SCAN_BS;

    k_zero<<<(N + 255) / 256, 256>>>(N);
    k_preppack<<<eb + pb, 256>>>(src, dst, ew, E, eb, Wx, bg, th, cb);
    k_scan1<<<nb, SCAN_BS>>>(N);
    k_scan2<<<1, MAX_SBLK>>>(nb);
    k_scan3<<<nb, SCAN_BS>>>(N);
    k_fill<<<eb, 256>>>(src, dst, ew, E);

    const int ab = (N * 16 + 255) / 256;
    k_agg<0><<<ab, 256>>>((const float4*)h, nullptr, (float4*)p_tx1, N);
    k_agg<1><<<ab, 256>>>((const float4*)p_tx1, (const float4*)h, (float4*)p_tx2, N);

    k_fused<<<(N + NPB - 1) / NPB, 256, SMEM_BYTES>>>(
        x, h, (const float*)p_tx1, (const float*)p_tx2, c, Wl, bl, out, N);
}

// round 12
// speedup vs baseline: 1.4583x; 1.4583x over previous
#include <cuda_runtime.h>
#include <math.h>

#define NNODES_MAX 100000
#define NEDGES_MAX 1600000
#define IN_DIM 128
#define HID 64
#define KTOT 320   // IN_DIM + 3*HID
#define NCOLS 256  // 4 gates * HID
#define KC 32
#define NCHUNK 10  // KTOT / KC
#define NPB 64
#define SCAN_BS 256
#define MAX_SBLK 512
#define SMEM_BYTES (2 * (NPB * KC + KC * NCOLS) * 4)   // 81920

// ---------------- scratch (static device globals; no allocation) ----------------
__device__ __align__(16) float g_deg [NNODES_MAX];
__device__ __align__(16) int   g_cnt [NNODES_MAX];
__device__ __align__(16) int   g_off [NNODES_MAX];   // block-LOCAL exclusive offset
__device__ __align__(16) int   g_cur [NNODES_MAX];   // ditto (fill adds block base)
__device__ __align__(16) int   g_bsum[MAX_SBLK];     // exclusive block bases
__device__ __align__(16) long long g_pay[NEDGES_MAX];   // {lw(f32)<<32 | src}
__device__ __align__(16) float g_Tx1 [NNODES_MAX * HID];
__device__ __align__(16) float g_Tx2 [NNODES_MAX * HID];
__device__ __align__(16) float g_Wp  [KTOT * NCOLS];
__device__ __align__(16) float g_biasp[NCOLS];

// ---------------- helpers ----------------
__device__ __forceinline__ float sigf(float v) { return 1.0f / (1.0f + expf(-v)); }

__device__ __forceinline__ unsigned long long ffma2(unsigned long long a,
                                                    unsigned long long b,
                                                    unsigned long long c) {
    unsigned long long d;
    asm("fma.rn.f32x2 %0, %1, %2, %3;" : "=l"(d) : "l"(a), "l"(b), "l"(c));
    return d;
}
__device__ __forceinline__ float2 u2f(unsigned long long u) {
    float2 f; asm("mov.b64 {%0,%1}, %2;" : "=f"(f.x), "=f"(f.y) : "l"(u)); return f;
}
__device__ __forceinline__ unsigned long long dup2(float v) {
    unsigned long long r; asm("mov.b64 %0, {%1, %1};" : "=l"(r) : "f"(v)); return r;
}
__device__ __forceinline__ void cp16(void* smem, const void* gmem) {
    unsigned sa = (unsigned)__cvta_generic_to_shared(smem);
    asm volatile("cp.async.cg.shared.global [%0], [%1], 16;" :: "r"(sa), "l"(gmem));
}
#define CP_COMMIT() asm volatile("cp.async.commit_group;" ::: "memory")
#define CP_WAIT0()  asm volatile("cp.async.wait_group 0;"  ::: "memory")

// ---------------- zero scratch + counters ----------------
__global__ void k_zero(int N) {
    int i = blockIdx.x * blockDim.x + threadIdx.x;
    if (i < N) { g_deg[i] = 0.0f; g_cnt[i] = 0; }
}

// ---------------- prep (deg + hist) fused with weight pack, split by block ----------------
__global__ void k_preppack(const int* __restrict__ src, const int* __restrict__ dst,
                           const float* __restrict__ ew, int E, int eb,
                           const float* __restrict__ Wx, const float* __restrict__ bg,
                           const float* __restrict__ theta, const float* __restrict__ convb) {
    int b = blockIdx.x;
    if (b < eb) {
        int e = b * 256 + threadIdx.x;
        if (e >= E) return;
        int s = src[e], d = dst[e];
        float w = (s == d) ? 0.0f : ew[e];
        if (w != 0.0f) atomicAdd(&g_deg[s], w);
        atomicAdd(&g_cnt[d], 1);
    } else {
        int idx = (b - eb) * 256 + threadIdx.x;
        if (idx >= KTOT * NCOLS) return;
        int k = idx / NCOLS, j = idx % NCOLS;
        int g = j >> 6, o = j & 63;
        float v;
        if (k < IN_DIM) {
            v = Wx[(g * IN_DIM + k) * HID + o];
        } else {
            int kk = k - IN_DIM;
            v = theta[((g * 3 + kk / HID) * HID + (kk % HID)) * HID + o];
        }
        g_Wp[idx] = v;
        if (idx < NCOLS) g_biasp[idx] = bg[idx] + convb[idx];
    }
}

// ---------------- scan: block-local exclusive offsets + block sums ----------------
__global__ void k_scan1(int N) {
    __shared__ int sm[SCAN_BS];
    int t = threadIdx.x;
    int i = blockIdx.x * SCAN_BS + t;
    int v = (i < N) ? g_cnt[i] : 0;
    sm[t] = v; __syncthreads();
    #pragma unroll
    for (int d = 1; d < SCAN_BS; d <<= 1) {
        int u = (t >= d) ? sm[t - d] : 0;
        __syncthreads();
        sm[t] += u;
        __syncthreads();
    }
    if (i < N) { int o = sm[t] - v; g_off[i] = o; g_cur[i] = o; }
    if (t == SCAN_BS - 1) g_bsum[blockIdx.x] = sm[t];
}
__global__ void k_scan2(int nb) {
    __shared__ int sm[MAX_SBLK];
    int t = threadIdx.x;
    int v = (t < nb) ? g_bsum[t] : 0;
    sm[t] = v; __syncthreads();
    #pragma unroll
    for (int d = 1; d < MAX_SBLK; d <<= 1) {
        int u = (t >= d) ? sm[t - d] : 0;
        __syncthreads();
        sm[t] += u;
        __syncthreads();
    }
    if (t < nb) g_bsum[t] = sm[t] - v;
}

// ---------------- fill CSR payload {src, lap_w} (adds block base on the fly) ----------------
__global__ void k_fill(const int* __restrict__ src, const int* __restrict__ dst,
                       const float* __restrict__ ew, int E) {
    int e = blockIdx.x * blockDim.x + threadIdx.x;
    if (e >= E) return;
    int s = src[e], d = dst[e];
    float w  = (s == d) ? 0.0f : ew[e];
    float ds = g_deg[s], dd = g_deg[d];
    float is = (ds > 0.0f) ? rsqrtf(ds) : 0.0f;
    float id = (dd > 0.0f) ? rsqrtf(dd) : 0.0f;
    float lw = -is * w * id;
    int pos = atomicAdd(&g_cur[d], 1) + g_bsum[d >> 8];   // SCAN_BS = 256
    g_pay[pos] = ((long long)(unsigned long long)__float_as_uint(lw) << 32)
                 | (unsigned)s;
}

// ---------------- aggregate: 8 threads/node, 2 float4 cols/thread, MLP=8 ----------------
template <int TX2>
__global__ __launch_bounds__(256) void k_agg(const float4* __restrict__ z,
                                             const float4* __restrict__ hsub,
                                             float4* __restrict__ outb,
                                             int N) {
    int gid = blockIdx.x * blockDim.x + threadIdx.x;
    int n = gid >> 3;
    if (n >= N) return;
    int c = (gid & 7) * 2;
    int j   = g_off[n] + g_bsum[n >> 8];
    int end = j + g_cnt[n];

    float4 a0 = make_float4(0.f, 0.f, 0.f, 0.f);
    float4 a1 = a0;
    for (; j + 3 < end; j += 4) {
        long long pp[4];
        #pragma unroll
        for (int u = 0; u < 4; ++u) pp[u] = g_pay[j + u];
        float4 v0[4], v1[4];
        float  ll[4];
        #pragma unroll
        for (int u = 0; u < 4; ++u) {
            int s = (int)(pp[u] & 0xffffffffLL);
            ll[u] = __uint_as_float((unsigned)((unsigned long long)pp[u] >> 32));
            v0[u] = z[(long)s * 16 + c];
            v1[u] = z[(long)s * 16 + c + 1];
        }
        #pragma unroll
        for (int u = 0; u < 4; ++u) {
            a0.x = fmaf(ll[u], v0[u].x, a0.x); a0.y = fmaf(ll[u], v0[u].y, a0.y);
            a0.z = fmaf(ll[u], v0[u].z, a0.z); a0.w = fmaf(ll[u], v0[u].w, a0.w);
            a1.x = fmaf(ll[u], v1[u].x, a1.x); a1.y = fmaf(ll[u], v1[u].y, a1.y);
            a1.z = fmaf(ll[u], v1[u].z, a1.z); a1.w = fmaf(ll[u], v1[u].w, a1.w);
        }
    }
    for (; j < end; ++j) {
        long long p0 = g_pay[j];
        int   s0 = (int)(p0 & 0xffffffffLL);
        float l0 = __uint_as_float((unsigned)((unsigned long long)p0 >> 32));
        float4 v0 = z[(long)s0 * 16 + c];
        float4 v1 = z[(long)s0 * 16 + c + 1];
        a0.x = fmaf(l0, v0.x, a0.x); a0.y = fmaf(l0, v0.y, a0.y);
        a0.z = fmaf(l0, v0.z, a0.z); a0.w = fmaf(l0, v0.w, a0.w);
        a1.x = fmaf(l0, v1.x, a1.x); a1.y = fmaf(l0, v1.y, a1.y);
        a1.z = fmaf(l0, v1.z, a1.z); a1.w = fmaf(l0, v1.w, a1.w);
    }
    if (TX2) {
        float4 h0 = hsub[(long)n * 16 + c];
        float4 h1 = hsub[(long)n * 16 + c + 1];
        a0.x = 2.0f * a0.x - h0.x; a0.y = 2.0f * a0.y - h0.y;
        a0.z = 2.0f * a0.z - h0.z; a0.w = 2.0f * a0.w - h0.w;
        a1.x = 2.0f * a1.x - h1.x; a1.y = 2.0f * a1.y - h1.y;
        a1.z = 2.0f * a1.z - h1.z; a1.w = 2.0f * a1.w - h1.w;
    }
    outb[(long)n * 16 + c]     = a0;
    outb[(long)n * 16 + c + 1] = a1;
}

// ---------------- fused GEMM (320->256), KC=32 double-buffered (R10-proven) ----------------
__global__ __launch_bounds__(256, 2) void k_fused(
    const float* __restrict__ x, const float* __restrict__ h,
    const float* __restrict__ tx1, const float* __restrict__ tx2,
    const float* __restrict__ c, const float* __restrict__ Wl,
    const float* __restrict__ bl, float* __restrict__ out, int N) {

    extern __shared__ __align__(16) float sm[];
    float* Xs0 = sm;                 // 2048 floats
    float* Xs1 = sm + NPB * KC;      // 2048
    float* Wsb = sm + 2 * NPB * KC;  // 2 x 8192

    const int tid = threadIdx.x;
    const int p  = tid & 31;
    const int ty = tid >> 5;
    const int nb = blockIdx.x * NPB;
    const int xn  = tid >> 2;
    const int xq0 = (tid & 3) * 2;
    const int gxn = nb + xn;

    unsigned long long acc[8][4];
    {
        unsigned long long bini[4];
        #pragma unroll
        for (int g = 0; g < 4; ++g)
            bini[g] = *reinterpret_cast<const unsigned long long*>(&g_biasp[g * 64 + 2 * p]);
        #pragma unroll
        for (int i = 0; i < 8; ++i)
            #pragma unroll
            for (int g = 0; g < 4; ++g) acc[i][g] = bini[g];
    }

    auto load_x = [&](int kc, float4& a, float4& b) {
        const float* sp; int ld, col;
        if (kc < 4)      { sp = x;   ld = IN_DIM; col = kc * KC; }
        else if (kc < 6) { sp = h;   ld = HID;    col = (kc - 4) * KC; }
        else if (kc < 8) { sp = tx1; ld = HID;    col = (kc - 6) * KC; }
        else             { sp = tx2; ld = HID;    col = (kc - 8) * KC; }
        if (gxn < N) {
            const float* base = sp + (long)gxn * ld + col;
            a = *reinterpret_cast<const float4*>(base + xq0 * 4);
            b = *reinterpret_cast<const float4*>(base + xq0 * 4 + 4);
        } else {
            a = make_float4(0.f, 0.f, 0.f, 0.f);
            b = a;
        }
    };
    auto store_x = [&](int buf, float4 a, float4 b) {
        float* X = buf ? Xs1 : Xs0;
        *reinterpret_cast<float4*>(&X[xn * KC + xq0 * 4])     = a;
        *reinterpret_cast<float4*>(&X[xn * KC + xq0 * 4 + 4]) = b;
    };
    auto issue_w = [&](int kc, int buf) {
        const float4* wp4 = reinterpret_cast<const float4*>(g_Wp + kc * KC * NCOLS);
        float4* ws4 = reinterpret_cast<float4*>(Wsb + buf * (KC * NCOLS));
        #pragma unroll
        for (int r = 0; r < 8; ++r)
            cp16(&ws4[tid + r * 256], &wp4[tid + r * 256]);
        CP_COMMIT();
    };

    issue_w(0, 0);
    {
        float4 a, b; load_x(0, a, b);
        store_x(0, a, b);
    }
    CP_WAIT0();
    __syncthreads();

    for (int kc = 0; kc < NCHUNK; ++kc) {
        const int cur = kc & 1;
        float4 xa, xb;
        if (kc < NCHUNK - 1) {
            issue_w(kc + 1, cur ^ 1);
            load_x(kc + 1, xa, xb);
        }
        {
            const unsigned long long* wr =
                reinterpret_cast<const unsigned long long*>(Wsb + cur * (KC * NCOLS));
            const float* xf = cur ? Xs1 : Xs0;
            for (int ko = 0; ko < KC; ko += 8) {
                #pragma unroll
                for (int k8 = 0; k8 < 8; ++k8) {
                    int kk = ko + k8;
                    unsigned long long a[8], b[4];
                    #pragma unroll
                    for (int i = 0; i < 8; ++i) a[i] = dup2(xf[(ty + 8 * i) * KC + kk]);
                    #pragma unroll
                    for (int g = 0; g < 4; ++g) b[g] = wr[kk * 128 + g * 32 + p];
                    #pragma unroll
                    for (int i = 0; i < 8; ++i)
                        #pragma unroll
                        for (int g = 0; g < 4; ++g) acc[i][g] = ffma2(a[i], b[g], acc[i][g]);
                }
            }
        }
        if (kc < NCHUNK - 1)
            store_x(cur ^ 1, xa, xb);
        CP_WAIT0();
        __syncthreads();
    }

    // ---- phase 2: gates + h0/c0 + relu(h0)@Wl + bl (reuse smem) ----
    float* Hs  = sm;          // [64][64]
    float* Wls = sm + 4096;   // [64][64]

    #pragma unroll
    for (int i = 0; i < 8; ++i) {
        int nl = ty + 8 * i;
        int n = nb + nl;
        float2 pi = u2f(acc[i][0]);
        float2 pf = u2f(acc[i][1]);
        float2 pt = u2f(acc[i][2]);
        float2 po = u2f(acc[i][3]);
        float r0 = 0.0f, r1 = 0.0f;
        if (n < N) {
            float2 cold = *reinterpret_cast<const float2*>(c + (long)n * HID + 2 * p);
            float ig0 = sigf(pi.x), ig1 = sigf(pi.y);
            float fg0 = sigf(pf.x), fg1 = sigf(pf.y);
            float tg0 = tanhf(pt.x), tg1 = tanhf(pt.y);
            float og0 = sigf(po.x), og1 = sigf(po.y);
            float c00 = fg0 * cold.x + ig0 * tg0;
            float c01 = fg1 * cold.y + ig1 * tg1;
            float h00 = og0 * tanhf(c00);
            float h01 = og1 * tanhf(c01);
            *reinterpret_cast<float2*>(out + (long)N * HID + (long)n * HID + 2 * p)
                = make_float2(h00, h01);
            *reinterpret_cast<float2*>(out + 2L * N * HID + (long)n * HID + 2 * p)
                = make_float2(c00, c01);
            r0 = fmaxf(h00, 0.0f);
            r1 = fmaxf(h01, 0.0f);
        }
        Hs[nl * 64 + 2 * p]     = r0;
        Hs[nl * 64 + 2 * p + 1] = r1;
    }
    {
        float4* wl4 = reinterpret_cast<float4*>(Wls);
        const float4* wlg = reinterpret_cast<const float4*>(Wl);
        #pragma unroll
        for (int r = 0; r < 4; ++r) wl4[tid + r * 256] = wlg[tid + r * 256];
    }
    __syncthreads();

    float o0[8], o1[8];
    {
        float b0 = bl[2 * p], b1 = bl[2 * p + 1];
        #pragma unroll
        for (int i = 0; i < 8; ++i) { o0[i] = b0; o1[i] = b1; }
    }
    for (int k = 0; k < 64; ++k) {
        float2 w = *reinterpret_cast<const float2*>(Wls + k * 64 + 2 * p);
        #pragma unroll
        for (int i = 0; i < 8; ++i) {
            float a = Hs[(ty + 8 * i) * 64 + k];
            o0[i] = fmaf(a, w.x, o0[i]);
            o1[i] = fmaf(a, w.y, o1[i]);
        }
    }
    #pragma unroll
    for (int i = 0; i < 8; ++i) {
        int n = nb + ty + 8 * i;
        if (n < N)
            *reinterpret_cast<float2*>(out + (long)n * HID + 2 * p) = make_float2(o0[i], o1[i]);
    }
}

// ---------------- launch ----------------
extern "C" void kernel_launch(void* const* d_in, const int* in_sizes, int n_in,
                              void* d_out, int out_size) {
    const float* x   = (const float*)d_in[0];
    const int*   ei  = (const int*)d_in[1];
    const float* ew  = (const float*)d_in[2];
    const float* h   = (const float*)d_in[3];
    const float* c   = (const float*)d_in[4];
    const float* Wx  = (const float*)d_in[5];
    const float* bg  = (const float*)d_in[6];
    const float* th  = (const float*)d_in[7];
    const float* cb  = (const float*)d_in[8];
    const float* Wl  = (const float*)d_in[9];
    const float* bl  = (const float*)d_in[10];
    float* out = (float*)d_out;

    const int N = in_sizes[0] / IN_DIM;
    const int E = in_sizes[1] / 2;
    const int* src = ei;
    const int* dst = ei + E;

    void *p_tx1, *p_tx2;
    cudaGetSymbolAddress(&p_tx1, g_Tx1);
    cudaGetSymbolAddress(&p_tx2, g_Tx2);

    static int smem_set = 0;
    if (!smem_set) {
        cudaFuncSetAttribute(k_fused, cudaFuncAttributeMaxDynamicSharedMemorySize,
                             SMEM_BYTES);
        smem_set = 1;
    }

    const int eb = (E + 255) / 256;
    const int pb = (KTOT * NCOLS + 255) / 256;
    const int nb = (N + SCAN_BS - 1) / SCAN_BS;

    k_zero<<<(N + 255) / 256, 256>>>(N);
    k_preppack<<<eb + pb, 256>>>(src, dst, ew, E, eb, Wx, bg, th, cb);
    k_scan1<<<nb, SCAN_BS>>>(N);
    k_scan2<<<1, MAX_SBLK>>>(nb);
    k_fill<<<eb, 256>>>(src, dst, ew, E);

    const int ab = (N * 8 + 255) / 256;
    k_agg<0><<<ab, 256>>>((const float4*)h, nullptr, (float4*)p_tx1, N);
    k_agg<1><<<ab, 256>>>((const float4*)p_tx1, (const float4*)h, (float4*)p_tx2, N);

    k_fused<<<(N + NPB - 1) / NPB, 256, SMEM_BYTES>>>(
        x, h, (const float*)p_tx1, (const float*)p_tx2, c, Wl, bl, out, N);
}

// round 13
// speedup vs baseline: 1.5023x; 1.0301x over previous
#include <cuda_runtime.h>
#include <math.h>

#define NNODES_MAX 100000
#define NEDGES_MAX 1600000
#define IN_DIM 128
#define HID 64
#define KTOT 320   // IN_DIM + 3*HID
#define NCOLS 256  // 4 gates * HID
#define KC 32
#define NCHUNK 10  // KTOT / KC
#define NPB 64
#define SCAN_BS 256
#define MAX_SBLK 512
#define SMEM_BYTES (2 * (NPB * KC + KC * NCOLS) * 4)   // 81920

// ---------------- scratch (static device globals; no allocation) ----------------
__device__ __align__(16) float g_deg [NNODES_MAX];
__device__ __align__(16) int   g_cnt [NNODES_MAX];
__device__ __align__(16) int   g_off [NNODES_MAX];   // block-LOCAL exclusive offset
__device__ __align__(16) int   g_cur [NNODES_MAX];   // ditto (fill adds block base)
__device__ __align__(16) int   g_bsum[MAX_SBLK];     // exclusive block bases
__device__ __align__(16) long long g_pay[NEDGES_MAX];   // {lw(f32)<<32 | src}
__device__ __align__(16) float g_Tx1 [NNODES_MAX * HID];
__device__ __align__(16) float g_Tx2 [NNODES_MAX * HID];
__device__ __align__(16) float g_Wp  [KTOT * NCOLS];
__device__ __align__(16) float g_biasp[NCOLS];

// ---------------- helpers ----------------
__device__ __forceinline__ float sigf(float v) { return 1.0f / (1.0f + expf(-v)); }

__device__ __forceinline__ unsigned long long ffma2(unsigned long long a,
                                                    unsigned long long b,
                                                    unsigned long long c) {
    unsigned long long d;
    asm("fma.rn.f32x2 %0, %1, %2, %3;" : "=l"(d) : "l"(a), "l"(b), "l"(c));
    return d;
}
__device__ __forceinline__ float2 u2f(unsigned long long u) {
    float2 f; asm("mov.b64 {%0,%1}, %2;" : "=f"(f.x), "=f"(f.y) : "l"(u)); return f;
}
__device__ __forceinline__ unsigned long long dup2(float v) {
    unsigned long long r; asm("mov.b64 %0, {%1, %1};" : "=l"(r) : "f"(v)); return r;
}
__device__ __forceinline__ void cp16(void* smem, const void* gmem) {
    unsigned sa = (unsigned)__cvta_generic_to_shared(smem);
    asm volatile("cp.async.cg.shared.global [%0], [%1], 16;" :: "r"(sa), "l"(gmem));
}
#define CP_COMMIT() asm volatile("cp.async.commit_group;" ::: "memory")
#define CP_WAIT0()  asm volatile("cp.async.wait_group 0;"  ::: "memory")

// ---------------- zero scratch + counters ----------------
__global__ void k_zero(int N) {
    int i = blockIdx.x * blockDim.x + threadIdx.x;
    if (i < N) { g_deg[i] = 0.0f; g_cnt[i] = 0; }
}

// ---------------- prep (deg + hist) fused with weight pack, split by block ----------------
__global__ void k_preppack(const int* __restrict__ src, const int* __restrict__ dst,
                           const float* __restrict__ ew, int E, int eb,
                           const float* __restrict__ Wx, const float* __restrict__ bg,
                           const float* __restrict__ theta, const float* __restrict__ convb) {
    int b = blockIdx.x;
    if (b < eb) {
        int e = b * 256 + threadIdx.x;
        if (e >= E) return;
        int s = src[e], d = dst[e];
        float w = (s == d) ? 0.0f : ew[e];
        if (w != 0.0f) atomicAdd(&g_deg[s], w);
        atomicAdd(&g_cnt[d], 1);
    } else {
        int idx = (b - eb) * 256 + threadIdx.x;
        if (idx >= KTOT * NCOLS) return;
        int k = idx / NCOLS, j = idx % NCOLS;
        int g = j >> 6, o = j & 63;
        float v;
        if (k < IN_DIM) {
            v = Wx[(g * IN_DIM + k) * HID + o];
        } else {
            int kk = k - IN_DIM;
            v = theta[((g * 3 + kk / HID) * HID + (kk % HID)) * HID + o];
        }
        g_Wp[idx] = v;
        if (idx < NCOLS) g_biasp[idx] = bg[idx] + convb[idx];
    }
}

// ---------------- scan: block-local exclusive offsets + block sums ----------------
__global__ void k_scan1(int N) {
    __shared__ int sm[SCAN_BS];
    int t = threadIdx.x;
    int i = blockIdx.x * SCAN_BS + t;
    int v = (i < N) ? g_cnt[i] : 0;
    sm[t] = v; __syncthreads();
    #pragma unroll
    for (int d = 1; d < SCAN_BS; d <<= 1) {
        int u = (t >= d) ? sm[t - d] : 0;
        __syncthreads();
        sm[t] += u;
        __syncthreads();
    }
    if (i < N) { int o = sm[t] - v; g_off[i] = o; g_cur[i] = o; }
    if (t == SCAN_BS - 1) g_bsum[blockIdx.x] = sm[t];
}
__global__ void k_scan2(int nb) {
    __shared__ int sm[MAX_SBLK];
    int t = threadIdx.x;
    int v = (t < nb) ? g_bsum[t] : 0;
    sm[t] = v; __syncthreads();
    #pragma unroll
    for (int d = 1; d < MAX_SBLK; d <<= 1) {
        int u = (t >= d) ? sm[t - d] : 0;
        __syncthreads();
        sm[t] += u;
        __syncthreads();
    }
    if (t < nb) g_bsum[t] = sm[t] - v;
}

// ---------------- fill CSR payload {src, lap_w} (adds block base on the fly) ----------------
__global__ void k_fill(const int* __restrict__ src, const int* __restrict__ dst,
                       const float* __restrict__ ew, int E) {
    int e = blockIdx.x * blockDim.x + threadIdx.x;
    if (e >= E) return;
    int s = src[e], d = dst[e];
    float w  = (s == d) ? 0.0f : ew[e];
    float ds = g_deg[s], dd = g_deg[d];
    float is = (ds > 0.0f) ? rsqrtf(ds) : 0.0f;
    float id = (dd > 0.0f) ? rsqrtf(dd) : 0.0f;
    float lw = -is * w * id;
    int pos = atomicAdd(&g_cur[d], 1) + g_bsum[d >> 8];   // SCAN_BS = 256
    g_pay[pos] = ((long long)(unsigned long long)__float_as_uint(lw) << 32)
                 | (unsigned)s;
}

// ---------------- aggregate: 16 threads/node, 1 float4 col/thread, MLP=8 (R10-proven) ----------------
template <int TX2>
__global__ __launch_bounds__(256) void k_agg(const float4* __restrict__ z,
                                             const float4* __restrict__ hsub,
                                             float4* __restrict__ outb,
                                             int N) {
    int gid = blockIdx.x * blockDim.x + threadIdx.x;
    int n = gid >> 4;
    if (n >= N) return;
    int c = gid & 15;
    int j   = g_off[n] + g_bsum[n >> 8];
    int end = j + g_cnt[n];

    float4 acc = make_float4(0.f, 0.f, 0.f, 0.f);
    for (; j + 7 < end; j += 8) {
        long long pp[8];
        #pragma unroll
        for (int u = 0; u < 8; ++u) pp[u] = g_pay[j + u];
        float4 vv[8];
        float  ll[8];
        #pragma unroll
        for (int u = 0; u < 8; ++u) {
            int s = (int)(pp[u] & 0xffffffffLL);
            ll[u] = __uint_as_float((unsigned)((unsigned long long)pp[u] >> 32));
            vv[u] = z[(long)s * 16 + c];
        }
        #pragma unroll
        for (int u = 0; u < 8; ++u) {
            acc.x = fmaf(ll[u], vv[u].x, acc.x);
            acc.y = fmaf(ll[u], vv[u].y, acc.y);
            acc.z = fmaf(ll[u], vv[u].z, acc.z);
            acc.w = fmaf(ll[u], vv[u].w, acc.w);
        }
    }
    for (; j < end; ++j) {
        long long p0 = g_pay[j];
        int   s0 = (int)(p0 & 0xffffffffLL);
        float l0 = __uint_as_float((unsigned)((unsigned long long)p0 >> 32));
        float4 v0 = z[(long)s0 * 16 + c];
        acc.x = fmaf(l0, v0.x, acc.x); acc.y = fmaf(l0, v0.y, acc.y);
        acc.z = fmaf(l0, v0.z, acc.z); acc.w = fmaf(l0, v0.w, acc.w);
    }
    if (TX2) {
        float4 hv = hsub[(long)n * 16 + c];
        acc.x = 2.0f * acc.x - hv.x; acc.y = 2.0f * acc.y - hv.y;
        acc.z = 2.0f * acc.z - hv.z; acc.w = 2.0f * acc.w - hv.w;
    }
    outb[(long)n * 16 + c] = acc;
}

// ---------------- fused GEMM (320->256), KC=32 double-buffered (R10-proven) ----------------
__global__ __launch_bounds__(256, 2) void k_fused(
    const float* __restrict__ x, const float* __restrict__ h,
    const float* __restrict__ tx1, const float* __restrict__ tx2,
    const float* __restrict__ c, const float* __restrict__ Wl,
    const float* __restrict__ bl, float* __restrict__ out, int N) {

    extern __shared__ __align__(16) float sm[];
    float* Xs0 = sm;                 // 2048 floats
    float* Xs1 = sm + NPB * KC;      // 2048
    float* Wsb = sm + 2 * NPB * KC;  // 2 x 8192

    const int tid = threadIdx.x;
    const int p  = tid & 31;
    const int ty = tid >> 5;
    const int nb = blockIdx.x * NPB;
    const int xn  = tid >> 2;
    const int xq0 = (tid & 3) * 2;
    const int gxn = nb + xn;

    unsigned long long acc[8][4];
    {
        unsigned long long bini[4];
        #pragma unroll
        for (int g = 0; g < 4; ++g)
            bini[g] = *reinterpret_cast<const unsigned long long*>(&g_biasp[g * 64 + 2 * p]);
        #pragma unroll
        for (int i = 0; i < 8; ++i)
            #pragma unroll
            for (int g = 0; g < 4; ++g) acc[i][g] = bini[g];
    }

    auto load_x = [&](int kc, float4& a, float4& b) {
        const float* sp; int ld, col;
        if (kc < 4)      { sp = x;   ld = IN_DIM; col = kc * KC; }
        else if (kc < 6) { sp = h;   ld = HID;    col = (kc - 4) * KC; }
        else if (kc < 8) { sp = tx1; ld = HID;    col = (kc - 6) * KC; }
        else             { sp = tx2; ld = HID;    col = (kc - 8) * KC; }
        if (gxn < N) {
            const float* base = sp + (long)gxn * ld + col;
            a = *reinterpret_cast<const float4*>(base + xq0 * 4);
            b = *reinterpret_cast<const float4*>(base + xq0 * 4 + 4);
        } else {
            a = make_float4(0.f, 0.f, 0.f, 0.f);
            b = a;
        }
    };
    auto store_x = [&](int buf, float4 a, float4 b) {
        float* X = buf ? Xs1 : Xs0;
        *reinterpret_cast<float4*>(&X[xn * KC + xq0 * 4])     = a;
        *reinterpret_cast<float4*>(&X[xn * KC + xq0 * 4 + 4]) = b;
    };
    auto issue_w = [&](int kc, int buf) {
        const float4* wp4 = reinterpret_cast<const float4*>(g_Wp + kc * KC * NCOLS);
        float4* ws4 = reinterpret_cast<float4*>(Wsb + buf * (KC * NCOLS));
        #pragma unroll
        for (int r = 0; r < 8; ++r)
            cp16(&ws4[tid + r * 256], &wp4[tid + r * 256]);
        CP_COMMIT();
    };

    issue_w(0, 0);
    {
        float4 a, b; load_x(0, a, b);
        store_x(0, a, b);
    }
    CP_WAIT0();
    __syncthreads();

    for (int kc = 0; kc < NCHUNK; ++kc) {
        const int cur = kc & 1;
        float4 xa, xb;
        if (kc < NCHUNK - 1) {
            issue_w(kc + 1, cur ^ 1);
            load_x(kc + 1, xa, xb);
        }
        {
            const unsigned long long* wr =
                reinterpret_cast<const unsigned long long*>(Wsb + cur * (KC * NCOLS));
            const float* xf = cur ? Xs1 : Xs0;
            for (int ko = 0; ko < KC; ko += 8) {
                #pragma unroll
                for (int k8 = 0; k8 < 8; ++k8) {
                    int kk = ko + k8;
                    unsigned long long a[8], b[4];
                    #pragma unroll
                    for (int i = 0; i < 8; ++i) a[i] = dup2(xf[(ty + 8 * i) * KC + kk]);
                    #pragma unroll
                    for (int g = 0; g < 4; ++g) b[g] = wr[kk * 128 + g * 32 + p];
                    #pragma unroll
                    for (int i = 0; i < 8; ++i)
                        #pragma unroll
                        for (int g = 0; g < 4; ++g) acc[i][g] = ffma2(a[i], b[g], acc[i][g]);
                }
            }
        }
        if (kc < NCHUNK - 1)
            store_x(cur ^ 1, xa, xb);
        CP_WAIT0();
        __syncthreads();
    }

    // ---- phase 2: gates + h0/c0 + relu(h0)@Wl + bl (reuse smem) ----
    float* Hs  = sm;          // [64][64]
    float* Wls = sm + 4096;   // [64][64]

    #pragma unroll
    for (int i = 0; i < 8; ++i) {
        int nl = ty + 8 * i;
        int n = nb + nl;
        float2 pi = u2f(acc[i][0]);
        float2 pf = u2f(acc[i][1]);
        float2 pt = u2f(acc[i][2]);
        float2 po = u2f(acc[i][3]);
        float r0 = 0.0f, r1 = 0.0f;
        if (n < N) {
            float2 cold = *reinterpret_cast<const float2*>(c + (long)n * HID + 2 * p);
            float ig0 = sigf(pi.x), ig1 = sigf(pi.y);
            float fg0 = sigf(pf.x), fg1 = sigf(pf.y);
            float tg0 = tanhf(pt.x), tg1 = tanhf(pt.y);
            float og0 = sigf(po.x), og1 = sigf(po.y);
            float c00 = fg0 * cold.x + ig0 * tg0;
            float c01 = fg1 * cold.y + ig1 * tg1;
            float h00 = og0 * tanhf(c00);
            float h01 = og1 * tanhf(c01);
            *reinterpret_cast<float2*>(out + (long)N * HID + (long)n * HID + 2 * p)
                = make_float2(h00, h01);
            *reinterpret_cast<float2*>(out + 2L * N * HID + (long)n * HID + 2 * p)
                = make_float2(c00, c01);
            r0 = fmaxf(h00, 0.0f);
            r1 = fmaxf(h01, 0.0f);
        }
        Hs[nl * 64 + 2 * p]     = r0;
        Hs[nl * 64 + 2 * p + 1] = r1;
    }
    {
        float4* wl4 = reinterpret_cast<float4*>(Wls);
        const float4* wlg = reinterpret_cast<const float4*>(Wl);
        #pragma unroll
        for (int r = 0; r < 4; ++r) wl4[tid + r * 256] = wlg[tid + r * 256];
    }
    __syncthreads();

    float o0[8], o1[8];
    {
        float b0 = bl[2 * p], b1 = bl[2 * p + 1];
        #pragma unroll
        for (int i = 0; i < 8; ++i) { o0[i] = b0; o1[i] = b1; }
    }
    for (int k = 0; k < 64; ++k) {
        float2 w = *reinterpret_cast<const float2*>(Wls + k * 64 + 2 * p);
        #pragma unroll
        for (int i = 0; i < 8; ++i) {
            float a = Hs[(ty + 8 * i) * 64 + k];
            o0[i] = fmaf(a, w.x, o0[i]);
            o1[i] = fmaf(a, w.y, o1[i]);
        }
    }
    #pragma unroll
    for (int i = 0; i < 8; ++i) {
        int n = nb + ty + 8 * i;
        if (n < N)
            *reinterpret_cast<float2*>(out + (long)n * HID + 2 * p) = make_float2(o0[i], o1[i]);
    }
}

// ---------------- launch ----------------
extern "C" void kernel_launch(void* const* d_in, const int* in_sizes, int n_in,
                              void* d_out, int out_size) {
    const float* x   = (const float*)d_in[0];
    const int*   ei  = (const int*)d_in[1];
    const float* ew  = (const float*)d_in[2];
    const float* h   = (const float*)d_in[3];
    const float* c   = (const float*)d_in[4];
    const float* Wx  = (const float*)d_in[5];
    const float* bg  = (const float*)d_in[6];
    const float* th  = (const float*)d_in[7];
    const float* cb  = (const float*)d_in[8];
    const float* Wl  = (const float*)d_in[9];
    const float* bl  = (const float*)d_in[10];
    float* out = (float*)d_out;

    const int N = in_sizes[0] / IN_DIM;
    const int E = in_sizes[1] / 2;
    const int* src = ei;
    const int* dst = ei + E;

    void *p_tx1, *p_tx2;
    cudaGetSymbolAddress(&p_tx1, g_Tx1);
    cudaGetSymbolAddress(&p_tx2, g_Tx2);

    static int smem_set = 0;
    if (!smem_set) {
        cudaFuncSetAttribute(k_fused, cudaFuncAttributeMaxDynamicSharedMemorySize,
                             SMEM_BYTES);
        smem_set = 1;
    }

    const int eb = (E + 255) / 256;
    const int pb = (KTOT * NCOLS + 255) / 256;
    const int nb = (N + SCAN_BS - 1) / SCAN_BS;

    k_zero<<<(N + 255) / 256, 256>>>(N);
    k_preppack<<<eb + pb, 256>>>(src, dst, ew, E, eb, Wx, bg, th, cb);
    k_scan1<<<nb, SCAN_BS>>>(N);
    k_scan2<<<1, MAX_SBLK>>>(nb);
    k_fill<<<eb, 256>>>(src, dst, ew, E);

    const int ab = (N * 16 + 255) / 256;
    k_agg<0><<<ab, 256>>>((const float4*)h, nullptr, (float4*)p_tx1, N);
    k_agg<1><<<ab, 256>>>((const float4*)p_tx1, (const float4*)h, (float4*)p_tx2, N);

    k_fused<<<(N + NPB - 1) / NPB, 256, SMEM_BYTES>>>(
        x, h, (const float*)p_tx1, (const float*)p_tx2, c, Wl, bl, out, N);
}

// round 14
// speedup vs baseline: 1.5092x; 1.0046x over previous
#include <cuda_runtime.h>
#include <math.h>

#define NNODES_MAX 100000
#define NEDGES_MAX 1600000
#define IN_DIM 128
#define HID 64
#define KTOT 320   // IN_DIM + 3*HID
#define NCOLS 256  // 4 gates * HID
#define KC 32
#define NCHUNK 10  // KTOT / KC
#define NPB 64
#define SCAN_BS 256
#define MAX_SBLK 512
#define SMEM_BYTES (2 * (NPB * KC + KC * NCOLS) * 4)   // 81920

// ---------------- scratch (static device globals; no allocation) ----------------
__device__ __align__(16) float g_deg [NNODES_MAX];
__device__ __align__(16) int   g_cnt [NNODES_MAX];
__device__ __align__(16) int   g_off [NNODES_MAX];   // block-LOCAL exclusive offset
__device__ __align__(16) int   g_cur [NNODES_MAX];   // ditto (fill adds block base)
__device__ __align__(16) int   g_bsum[MAX_SBLK];     // exclusive block bases
__device__ __align__(16) long long g_pay[NEDGES_MAX];   // {lw(f32)<<32 | src}
__device__ __align__(16) float g_Tx1 [NNODES_MAX * HID];
__device__ __align__(16) float g_Tx2 [NNODES_MAX * HID];
__device__ __align__(16) float g_Wp  [KTOT * NCOLS];
__device__ __align__(16) float g_biasp[NCOLS];

// ---------------- helpers ----------------
__device__ __forceinline__ float sigf(float v) { return 1.0f / (1.0f + expf(-v)); }

__device__ __forceinline__ unsigned long long ffma2(unsigned long long a,
                                                    unsigned long long b,
                                                    unsigned long long c) {
    unsigned long long d;
    asm("fma.rn.f32x2 %0, %1, %2, %3;" : "=l"(d) : "l"(a), "l"(b), "l"(c));
    return d;
}
__device__ __forceinline__ float2 u2f(unsigned long long u) {
    float2 f; asm("mov.b64 {%0,%1}, %2;" : "=f"(f.x), "=f"(f.y) : "l"(u)); return f;
}
__device__ __forceinline__ unsigned long long dup2(float v) {
    unsigned long long r; asm("mov.b64 %0, {%1, %1};" : "=l"(r) : "f"(v)); return r;
}
__device__ __forceinline__ void cp16(void* smem, const void* gmem) {
    unsigned sa = (unsigned)__cvta_generic_to_shared(smem);
    asm volatile("cp.async.cg.shared.global [%0], [%1], 16;" :: "r"(sa), "l"(gmem));
}
#define CP_COMMIT() asm volatile("cp.async.commit_group;" ::: "memory")
#define CP_WAIT0()  asm volatile("cp.async.wait_group 0;"  ::: "memory")

// ---------------- zero scratch + counters ----------------
__global__ void k_zero(int N) {
    int i = blockIdx.x * blockDim.x + threadIdx.x;
    if (i < N) { g_deg[i] = 0.0f; g_cnt[i] = 0; }
}

// ---------------- prep (deg + hist) fused with weight pack, split by block ----------------
__global__ void k_preppack(const int* __restrict__ src, const int* __restrict__ dst,
                           const float* __restrict__ ew, int E, int eb,
                           const float* __restrict__ Wx, const float* __restrict__ bg,
                           const float* __restrict__ theta, const float* __restrict__ convb) {
    int b = blockIdx.x;
    if (b < eb) {
        int e = b * 256 + threadIdx.x;
        if (e >= E) return;
        int s = src[e], d = dst[e];
        float w = (s == d) ? 0.0f : ew[e];
        if (w != 0.0f) atomicAdd(&g_deg[s], w);
        atomicAdd(&g_cnt[d], 1);
    } else {
        int idx = (b - eb) * 256 + threadIdx.x;
        if (idx >= KTOT * NCOLS) return;
        int k = idx / NCOLS, j = idx % NCOLS;
        int g = j >> 6, o = j & 63;
        float v;
        if (k < IN_DIM) {
            v = Wx[(g * IN_DIM + k) * HID + o];
        } else {
            int kk = k - IN_DIM;
            v = theta[((g * 3 + kk / HID) * HID + (kk % HID)) * HID + o];
        }
        g_Wp[idx] = v;
        if (idx < NCOLS) g_biasp[idx] = bg[idx] + convb[idx];
    }
}

// ---------------- scan: block-local exclusive offsets + block sums ----------------
__global__ void k_scan1(int N) {
    __shared__ int sm[SCAN_BS];
    int t = threadIdx.x;
    int i = blockIdx.x * SCAN_BS + t;
    int v = (i < N) ? g_cnt[i] : 0;
    sm[t] = v; __syncthreads();
    #pragma unroll
    for (int d = 1; d < SCAN_BS; d <<= 1) {
        int u = (t >= d) ? sm[t - d] : 0;
        __syncthreads();
        sm[t] += u;
        __syncthreads();
    }
    if (i < N) { int o = sm[t] - v; g_off[i] = o; g_cur[i] = o; }
    if (t == SCAN_BS - 1) g_bsum[blockIdx.x] = sm[t];
}
__global__ void k_scan2(int nb) {
    __shared__ int sm[MAX_SBLK];
    int t = threadIdx.x;
    int v = (t < nb) ? g_bsum[t] : 0;
    sm[t] = v; __syncthreads();
    #pragma unroll
    for (int d = 1; d < MAX_SBLK; d <<= 1) {
        int u = (t >= d) ? sm[t - d] : 0;
        __syncthreads();
        sm[t] += u;
        __syncthreads();
    }
    if (t < nb) g_bsum[t] = sm[t] - v;
}

// ---------------- fill CSR payload {src, lap_w} (adds block base on the fly) ----------------
__global__ void k_fill(const int* __restrict__ src, const int* __restrict__ dst,
                       const float* __restrict__ ew, int E) {
    int e = blockIdx.x * blockDim.x + threadIdx.x;
    if (e >= E) return;
    int s = src[e], d = dst[e];
    float w  = (s == d) ? 0.0f : ew[e];
    float ds = g_deg[s], dd = g_deg[d];
    float is = (ds > 0.0f) ? rsqrtf(ds) : 0.0f;
    float id = (dd > 0.0f) ? rsqrtf(dd) : 0.0f;
    float lw = -is * w * id;
    int pos = atomicAdd(&g_cur[d], 1) + g_bsum[d >> 8];   // SCAN_BS = 256
    g_pay[pos] = ((long long)(unsigned long long)__float_as_uint(lw) << 32)
                 | (unsigned)s;
}

// ---------------- aggregate: 16 threads/node, 1 float4 col/thread, MLP=8 ----------------
template <int TX2>
__global__ __launch_bounds__(256) void k_agg(const float4* __restrict__ z,
                                             const float4* __restrict__ hsub,
                                             float4* __restrict__ outb,
                                             int N) {
    int gid = blockIdx.x * blockDim.x + threadIdx.x;
    int n = gid >> 4;
    if (n >= N) return;
    int c = gid & 15;
    int j   = g_off[n] + g_bsum[n >> 8];
    int end = j + g_cnt[n];

    float4 acc = make_float4(0.f, 0.f, 0.f, 0.f);
    for (; j + 7 < end; j += 8) {
        long long pp[8];
        #pragma unroll
        for (int u = 0; u < 8; ++u) pp[u] = g_pay[j + u];
        float4 vv[8];
        float  ll[8];
        #pragma unroll
        for (int u = 0; u < 8; ++u) {
            int s = (int)(pp[u] & 0xffffffffLL);
            ll[u] = __uint_as_float((unsigned)((unsigned long long)pp[u] >> 32));
            vv[u] = z[(long)s * 16 + c];
        }
        #pragma unroll
        for (int u = 0; u < 8; ++u) {
            acc.x = fmaf(ll[u], vv[u].x, acc.x);
            acc.y = fmaf(ll[u], vv[u].y, acc.y);
            acc.z = fmaf(ll[u], vv[u].z, acc.z);
            acc.w = fmaf(ll[u], vv[u].w, acc.w);
        }
    }
    for (; j < end; ++j) {
        long long p0 = g_pay[j];
        int   s0 = (int)(p0 & 0xffffffffLL);
        float l0 = __uint_as_float((unsigned)((unsigned long long)p0 >> 32));
        float4 v0 = z[(long)s0 * 16 + c];
        acc.x = fmaf(l0, v0.x, acc.x); acc.y = fmaf(l0, v0.y, acc.y);
        acc.z = fmaf(l0, v0.z, acc.z); acc.w = fmaf(l0, v0.w, acc.w);
    }
    if (TX2) {
        float4 hv = hsub[(long)n * 16 + c];
        acc.x = 2.0f * acc.x - hv.x; acc.y = 2.0f * acc.y - hv.y;
        acc.z = 2.0f * acc.z - hv.z; acc.w = 2.0f * acc.w - hv.w;
    }
    outb[(long)n * 16 + c] = acc;
}

// ---------------- fused GEMM (320->256), KC=32 double-buffered, PDL-gated tx2 ----------------
// Launched with programmatic stream serialization: overlaps with k_agg<1>.
// tx2 is only touched from chunk 8 on; griddepcontrol.wait before prefetching it.
__global__ __launch_bounds__(256, 2) void k_fused(
    const float* __restrict__ x, const float* __restrict__ h,
    const float* __restrict__ tx1, const float* __restrict__ tx2,
    const float* __restrict__ c, const float* __restrict__ Wl,
    const float* __restrict__ bl, float* __restrict__ out, int N) {

    extern __shared__ __align__(16) float sm[];
    float* Xs0 = sm;                 // 2048 floats
    float* Xs1 = sm + NPB * KC;      // 2048
    float* Wsb = sm + 2 * NPB * KC;  // 2 x 8192

    const int tid = threadIdx.x;
    const int p  = tid & 31;
    const int ty = tid >> 5;
    const int nb = blockIdx.x * NPB;
    const int xn  = tid >> 2;
    const int xq0 = (tid & 3) * 2;
    const int gxn = nb + xn;

    unsigned long long acc[8][4];
    {
        unsigned long long bini[4];
        #pragma unroll
        for (int g = 0; g < 4; ++g)
            bini[g] = *reinterpret_cast<const unsigned long long*>(&g_biasp[g * 64 + 2 * p]);
        #pragma unroll
        for (int i = 0; i < 8; ++i)
            #pragma unroll
            for (int g = 0; g < 4; ++g) acc[i][g] = bini[g];
    }

    auto load_x = [&](int kc, float4& a, float4& b) {
        const float* sp; int ld, col;
        if (kc < 4)      { sp = x;   ld = IN_DIM; col = kc * KC; }
        else if (kc < 6) { sp = h;   ld = HID;    col = (kc - 4) * KC; }
        else if (kc < 8) { sp = tx1; ld = HID;    col = (kc - 6) * KC; }
        else             { sp = tx2; ld = HID;    col = (kc - 8) * KC; }
        if (gxn < N) {
            const float* base = sp + (long)gxn * ld + col;
            a = *reinterpret_cast<const float4*>(base + xq0 * 4);
            b = *reinterpret_cast<const float4*>(base + xq0 * 4 + 4);
        } else {
            a = make_float4(0.f, 0.f, 0.f, 0.f);
            b = a;
        }
    };
    auto store_x = [&](int buf, float4 a, float4 b) {
        float* X = buf ? Xs1 : Xs0;
        *reinterpret_cast<float4*>(&X[xn * KC + xq0 * 4])     = a;
        *reinterpret_cast<float4*>(&X[xn * KC + xq0 * 4 + 4]) = b;
    };
    auto issue_w = [&](int kc, int buf) {
        const float4* wp4 = reinterpret_cast<const float4*>(g_Wp + kc * KC * NCOLS);
        float4* ws4 = reinterpret_cast<float4*>(Wsb + buf * (KC * NCOLS));
        #pragma unroll
        for (int r = 0; r < 8; ++r)
            cp16(&ws4[tid + r * 256], &wp4[tid + r * 256]);
        CP_COMMIT();
    };

    issue_w(0, 0);
    {
        float4 a, b; load_x(0, a, b);
        store_x(0, a, b);
    }
    CP_WAIT0();
    __syncthreads();

    for (int kc = 0; kc < NCHUNK; ++kc) {
        const int cur = kc & 1;
        float4 xa, xb;
        if (kc < NCHUNK - 1) {
            if (kc == 7) {
                // chunk 8 (first tx2 chunk) is prefetched now — wait for k_agg<1>
                asm volatile("griddepcontrol.wait;" ::: "memory");
            }
            issue_w(kc + 1, cur ^ 1);
            load_x(kc + 1, xa, xb);
        }
        {
            const unsigned long long* wr =
                reinterpret_cast<const unsigned long long*>(Wsb + cur * (KC * NCOLS));
            const float* xf = cur ? Xs1 : Xs0;
            for (int ko = 0; ko < KC; ko += 8) {
                #pragma unroll
                for (int k8 = 0; k8 < 8; ++k8) {
                    int kk = ko + k8;
                    unsigned long long a[8], b[4];
                    #pragma unroll
                    for (int i = 0; i < 8; ++i) a[i] = dup2(xf[(ty + 8 * i) * KC + kk]);
                    #pragma unroll
                    for (int g = 0; g < 4; ++g) b[g] = wr[kk * 128 + g * 32 + p];
                    #pragma unroll
                    for (int i = 0; i < 8; ++i)
                        #pragma unroll
                        for (int g = 0; g < 4; ++g) acc[i][g] = ffma2(a[i], b[g], acc[i][g]);
                }
            }
        }
        if (kc < NCHUNK - 1)
            store_x(cur ^ 1, xa, xb);
        CP_WAIT0();
        __syncthreads();
    }

    // ---- phase 2: gates + h0/c0 + relu(h0)@Wl + bl (reuse smem) ----
    float* Hs  = sm;          // [64][64]
    float* Wls = sm + 4096;   // [64][64]

    #pragma unroll
    for (int i = 0; i < 8; ++i) {
        int nl = ty + 8 * i;
        int n = nb + nl;
        float2 pi = u2f(acc[i][0]);
        float2 pf = u2f(acc[i][1]);
        float2 pt = u2f(acc[i][2]);
        float2 po = u2f(acc[i][3]);
        float r0 = 0.0f, r1 = 0.0f;
        if (n < N) {
            float2 cold = *reinterpret_cast<const float2*>(c + (long)n * HID + 2 * p);
            float ig0 = sigf(pi.x), ig1 = sigf(pi.y);
            float fg0 = sigf(pf.x), fg1 = sigf(pf.y);
            float tg0 = tanhf(pt.x), tg1 = tanhf(pt.y);
            float og0 = sigf(po.x), og1 = sigf(po.y);
            float c00 = fg0 * cold.x + ig0 * tg0;
            float c01 = fg1 * cold.y + ig1 * tg1;
            float h00 = og0 * tanhf(c00);
            float h01 = og1 * tanhf(c01);
            *reinterpret_cast<float2*>(out + (long)N * HID + (long)n * HID + 2 * p)
                = make_float2(h00, h01);
            *reinterpret_cast<float2*>(out + 2L * N * HID + (long)n * HID + 2 * p)
                = make_float2(c00, c01);
            r0 = fmaxf(h00, 0.0f);
            r1 = fmaxf(h01, 0.0f);
        }
        Hs[nl * 64 + 2 * p]     = r0;
        Hs[nl * 64 + 2 * p + 1] = r1;
    }
    {
        float4* wl4 = reinterpret_cast<float4*>(Wls);
        const float4* wlg = reinterpret_cast<const float4*>(Wl);
        #pragma unroll
        for (int r = 0; r < 4; ++r) wl4[tid + r * 256] = wlg[tid + r * 256];
    }
    __syncthreads();

    float o0[8], o1[8];
    {
        float b0 = bl[2 * p], b1 = bl[2 * p + 1];
        #pragma unroll
        for (int i = 0; i < 8; ++i) { o0[i] = b0; o1[i] = b1; }
    }
    for (int k = 0; k < 64; ++k) {
        float2 w = *reinterpret_cast<const float2*>(Wls + k * 64 + 2 * p);
        #pragma unroll
        for (int i = 0; i < 8; ++i) {
            float a = Hs[(ty + 8 * i) * 64 + k];
            o0[i] = fmaf(a, w.x, o0[i]);
            o1[i] = fmaf(a, w.y, o1[i]);
        }
    }
    #pragma unroll
    for (int i = 0; i < 8; ++i) {
        int n = nb + ty + 8 * i;
        if (n < N)
            *reinterpret_cast<float2*>(out + (long)n * HID + 2 * p) = make_float2(o0[i], o1[i]);
    }
}

// ---------------- launch ----------------
extern "C" void kernel_launch(void* const* d_in, const int* in_sizes, int n_in,
                              void* d_out, int out_size) {
    const float* x   = (const float*)d_in[0];
    const int*   ei  = (const int*)d_in[1];
    const float* ew  = (const float*)d_in[2];
    const float* h   = (const float*)d_in[3];
    const float* c   = (const float*)d_in[4];
    const float* Wx  = (const float*)d_in[5];
    const float* bg  = (const float*)d_in[6];
    const float* th  = (const float*)d_in[7];
    const float* cb  = (const float*)d_in[8];
    const float* Wl  = (const float*)d_in[9];
    const float* bl  = (const float*)d_in[10];
    float* out = (float*)d_out;

    const int N = in_sizes[0] / IN_DIM;
    const int E = in_sizes[1] / 2;
    const int* src = ei;
    const int* dst = ei + E;

    void *p_tx1, *p_tx2;
    cudaGetSymbolAddress(&p_tx1, g_Tx1);
    cudaGetSymbolAddress(&p_tx2, g_Tx2);

    static int smem_set = 0;
    if (!smem_set) {
        cudaFuncSetAttribute(k_fused, cudaFuncAttributeMaxDynamicSharedMemorySize,
                             SMEM_BYTES);
        smem_set = 1;
    }

    const int eb = (E + 255) / 256;
    const int pb = (KTOT * NCOLS + 255) / 256;
    const int nb = (N + SCAN_BS - 1) / SCAN_BS;

    k_zero<<<(N + 255) / 256, 256>>>(N);
    k_preppack<<<eb + pb, 256>>>(src, dst, ew, E, eb, Wx, bg, th, cb);
    k_scan1<<<nb, SCAN_BS>>>(N);
    k_scan2<<<1, MAX_SBLK>>>(nb);
    k_fill<<<eb, 256>>>(src, dst, ew, E);

    const int ab = (N * 16 + 255) / 256;
    k_agg<0><<<ab, 256>>>((const float4*)h, nullptr, (float4*)p_tx1, N);
    k_agg<1><<<ab, 256>>>((const float4*)p_tx1, (const float4*)h, (float4*)p_tx2, N);

    // k_fused with programmatic dependent launch: starts while k_agg<1> runs;
    // griddepcontrol.wait inside gates the tx2 chunks on agg<1> completion.
    {
        cudaLaunchConfig_t cfg = {};
        cfg.gridDim  = dim3((N + NPB - 1) / NPB, 1, 1);
        cfg.blockDim = dim3(256, 1, 1);
        cfg.dynamicSmemBytes = SMEM_BYTES;
        cfg.stream = 0;
        cudaLaunchAttribute attr[1];
        attr[0].id = cudaLaunchAttributeProgrammaticStreamSerialization;
        attr[0].val.programmaticStreamSerializationAllowed = 1;
        cfg.attrs = attr;
        cfg.numAttrs = 1;
        cudaLaunchKernelEx(&cfg, k_fused,
                           x, h, (const float*)p_tx1, (const float*)p_tx2,
                           c, Wl, bl, out, N);
    }
}

// round 15
// speedup vs baseline: 1.5245x; 1.0101x over previous
#include <cuda_runtime.h>
#include <math.h>

#define NNODES_MAX 100000
#define NEDGES_MAX 1600000
#define IN_DIM 128
#define HID 64
#define KTOT 320   // IN_DIM + 3*HID
#define NCOLS 256  // 4 gates * HID
#define KC 32
#define NCHUNK 10  // KTOT / KC
#define NPB 64
#define SCAN_BS 256
#define MAX_SBLK 512
#define SMEM_BYTES (2 * (NPB * KC + KC * NCOLS) * 4)   // 81920

#define PDL_WAIT()    asm volatile("griddepcontrol.wait;" ::: "memory")
#define PDL_TRIGGER() asm volatile("griddepcontrol.launch_dependents;" ::: "memory")

// ---------------- scratch (static device globals; no allocation) ----------------
__device__ __align__(16) float g_deg [NNODES_MAX];
__device__ __align__(16) int   g_cnt [NNODES_MAX];
__device__ __align__(16) int   g_off [NNODES_MAX];   // block-LOCAL exclusive offset
__device__ __align__(16) int   g_cur [NNODES_MAX];   // ditto (fill adds block base)
__device__ __align__(16) int   g_bsum[MAX_SBLK];     // exclusive block bases
__device__ __align__(16) long long g_pay[NEDGES_MAX];   // {lw(f32)<<32 | src}
__device__ __align__(16) float g_Tx1 [NNODES_MAX * HID];
__device__ __align__(16) float g_Tx2 [NNODES_MAX * HID];
__device__ __align__(16) float g_Wp  [KTOT * NCOLS];
__device__ __align__(16) float g_biasp[NCOLS];

// ---------------- helpers ----------------
__device__ __forceinline__ float sigf(float v) { return 1.0f / (1.0f + expf(-v)); }

__device__ __forceinline__ unsigned long long ffma2(unsigned long long a,
                                                    unsigned long long b,
                                                    unsigned long long c) {
    unsigned long long d;
    asm("fma.rn.f32x2 %0, %1, %2, %3;" : "=l"(d) : "l"(a), "l"(b), "l"(c));
    return d;
}
__device__ __forceinline__ float2 u2f(unsigned long long u) {
    float2 f; asm("mov.b64 {%0,%1}, %2;" : "=f"(f.x), "=f"(f.y) : "l"(u)); return f;
}
__device__ __forceinline__ unsigned long long dup2(float v) {
    unsigned long long r; asm("mov.b64 %0, {%1, %1};" : "=l"(r) : "f"(v)); return r;
}
__device__ __forceinline__ void cp16(void* smem, const void* gmem) {
    unsigned sa = (unsigned)__cvta_generic_to_shared(smem);
    asm volatile("cp.async.cg.shared.global [%0], [%1], 16;" :: "r"(sa), "l"(gmem));
}
#define CP_COMMIT() asm volatile("cp.async.commit_group;" ::: "memory")
#define CP_WAIT0()  asm volatile("cp.async.wait_group 0;"  ::: "memory")

// ---------------- zero scratch + counters ----------------
__global__ void k_zero(int N) {
    PDL_TRIGGER();
    int i = blockIdx.x * blockDim.x + threadIdx.x;
    if (i < N) { g_deg[i] = 0.0f; g_cnt[i] = 0; }
}

// ---------------- prep (deg + hist) fused with weight pack, split by block ----------------
__global__ void k_preppack(const int* __restrict__ src, const int* __restrict__ dst,
                           const float* __restrict__ ew, int E, int eb,
                           const float* __restrict__ Wx, const float* __restrict__ bg,
                           const float* __restrict__ theta, const float* __restrict__ convb) {
    int b = blockIdx.x;
    if (b < eb) {
        PDL_WAIT();        // needs g_deg/g_cnt zeroed
        PDL_TRIGGER();
        int e = b * 256 + threadIdx.x;
        if (e >= E) return;
        int s = src[e], d = dst[e];
        float w = (s == d) ? 0.0f : ew[e];
        if (w != 0.0f) atomicAdd(&g_deg[s], w);
        atomicAdd(&g_cnt[d], 1);
    } else {
        PDL_TRIGGER();     // pack half independent of k_zero
        int idx = (b - eb) * 256 + threadIdx.x;
        if (idx >= KTOT * NCOLS) return;
        int k = idx / NCOLS, j = idx % NCOLS;
        int g = j >> 6, o = j & 63;
        float v;
        if (k < IN_DIM) {
            v = Wx[(g * IN_DIM + k) * HID + o];
        } else {
            int kk = k - IN_DIM;
            v = theta[((g * 3 + kk / HID) * HID + (kk % HID)) * HID + o];
        }
        g_Wp[idx] = v;
        if (idx < NCOLS) g_biasp[idx] = bg[idx] + convb[idx];
    }
}

// ---------------- scan: block-local exclusive offsets + block sums ----------------
__global__ void k_scan1(int N) {
    PDL_WAIT();            // needs g_cnt from preppack
    PDL_TRIGGER();
    __shared__ int sm[SCAN_BS];
    int t = threadIdx.x;
    int i = blockIdx.x * SCAN_BS + t;
    int v = (i < N) ? g_cnt[i] : 0;
    sm[t] = v; __syncthreads();
    #pragma unroll
    for (int d = 1; d < SCAN_BS; d <<= 1) {
        int u = (t >= d) ? sm[t - d] : 0;
        __syncthreads();
        sm[t] += u;
        __syncthreads();
    }
    if (i < N) { int o = sm[t] - v; g_off[i] = o; g_cur[i] = o; }
    if (t == SCAN_BS - 1) g_bsum[blockIdx.x] = sm[t];
}
__global__ void k_scan2(int nb) {
    PDL_WAIT();            // needs g_bsum from scan1
    PDL_TRIGGER();
    __shared__ int sm[MAX_SBLK];
    int t = threadIdx.x;
    int v = (t < nb) ? g_bsum[t] : 0;
    sm[t] = v; __syncthreads();
    #pragma unroll
    for (int d = 1; d < MAX_SBLK; d <<= 1) {
        int u = (t >= d) ? sm[t - d] : 0;
        __syncthreads();
        sm[t] += u;
        __syncthreads();
    }
    if (t < nb) g_bsum[t] = sm[t] - v;
}

// ---------------- fill CSR payload {src, lap_w} (adds block base on the fly) ----------------
__global__ void k_fill(const int* __restrict__ src, const int* __restrict__ dst,
                       const float* __restrict__ ew, int E) {
    PDL_WAIT();            // needs g_deg, g_cur, g_bsum
    PDL_TRIGGER();
    int e = blockIdx.x * blockDim.x + threadIdx.x;
    if (e >= E) return;
    int s = src[e], d = dst[e];
    float w  = (s == d) ? 0.0f : ew[e];
    float ds = g_deg[s], dd = g_deg[d];
    float is = (ds > 0.0f) ? rsqrtf(ds) : 0.0f;
    float id = (dd > 0.0f) ? rsqrtf(dd) : 0.0f;
    float lw = -is * w * id;
    int pos = atomicAdd(&g_cur[d], 1) + g_bsum[d >> 8];   // SCAN_BS = 256
    g_pay[pos] = ((long long)(unsigned long long)__float_as_uint(lw) << 32)
                 | (unsigned)s;
}

// ---------------- aggregate: 16 threads/node, 1 float4 col/thread, MLP=8 ----------------
template <int TX2>
__global__ __launch_bounds__(256) void k_agg(const float4* __restrict__ z,
                                             const float4* __restrict__ hsub,
                                             float4* __restrict__ outb,
                                             int N) {
    PDL_WAIT();            // needs g_pay (fill) resp. tx1 (agg<0>)
    PDL_TRIGGER();         // in agg<1>: releases k_fused to overlap chunks 0-7
    int gid = blockIdx.x * blockDim.x + threadIdx.x;
    int n = gid >> 4;
    if (n >= N) return;
    int c = gid & 15;
    int j   = g_off[n] + g_bsum[n >> 8];
    int end = j + g_cnt[n];

    float4 acc = make_float4(0.f, 0.f, 0.f, 0.f);
    for (; j + 7 < end; j += 8) {
        long long pp[8];
        #pragma unroll
        for (int u = 0; u < 8; ++u) pp[u] = g_pay[j + u];
        float4 vv[8];
        float  ll[8];
        #pragma unroll
        for (int u = 0; u < 8; ++u) {
            int s = (int)(pp[u] & 0xffffffffLL);
            ll[u] = __uint_as_float((unsigned)((unsigned long long)pp[u] >> 32));
            vv[u] = z[(long)s * 16 + c];
        }
        #pragma unroll
        for (int u = 0; u < 8; ++u) {
            acc.x = fmaf(ll[u], vv[u].x, acc.x);
            acc.y = fmaf(ll[u], vv[u].y, acc.y);
            acc.z = fmaf(ll[u], vv[u].z, acc.z);
            acc.w = fmaf(ll[u], vv[u].w, acc.w);
        }
    }
    for (; j < end; ++j) {
        long long p0 = g_pay[j];
        int   s0 = (int)(p0 & 0xffffffffLL);
        float l0 = __uint_as_float((unsigned)((unsigned long long)p0 >> 32));
        float4 v0 = z[(long)s0 * 16 + c];
        acc.x = fmaf(l0, v0.x, acc.x); acc.y = fmaf(l0, v0.y, acc.y);
        acc.z = fmaf(l0, v0.z, acc.z); acc.w = fmaf(l0, v0.w, acc.w);
    }
    if (TX2) {
        float4 hv = hsub[(long)n * 16 + c];
        acc.x = 2.0f * acc.x - hv.x; acc.y = 2.0f * acc.y - hv.y;
        acc.z = 2.0f * acc.z - hv.z; acc.w = 2.0f * acc.w - hv.w;
    }
    outb[(long)n * 16 + c] = acc;
}

// ---------------- fused GEMM (320->256), KC=32 double-buffered, PDL-gated tx2 ----------------
// Overlaps with k_agg<1> (trigger at agg entry). tx2 only touched from chunk 8;
// griddepcontrol.wait before prefetching it. x/h/tx1/g_Wp reads are safe
// transitively (all pre-agg<1> kernels complete before agg<1> passes its wait,
// which precedes the trigger that launches this kernel).
__global__ __launch_bounds__(256, 2) void k_fused(
    const float* __restrict__ x, const float* __restrict__ h,
    const float* __restrict__ tx1, const float* __restrict__ tx2,
    const float* __restrict__ c, const float* __restrict__ Wl,
    const float* __restrict__ bl, float* __restrict__ out, int N) {

    extern __shared__ __align__(16) float sm[];
    float* Xs0 = sm;                 // 2048 floats
    float* Xs1 = sm + NPB * KC;      // 2048
    float* Wsb = sm + 2 * NPB * KC;  // 2 x 8192

    const int tid = threadIdx.x;
    const int p  = tid & 31;
    const int ty = tid >> 5;
    const int nb = blockIdx.x * NPB;
    const int xn  = tid >> 2;
    const int xq0 = (tid & 3) * 2;
    const int gxn = nb + xn;

    unsigned long long acc[8][4];
    {
        unsigned long long bini[4];
        #pragma unroll
        for (int g = 0; g < 4; ++g)
            bini[g] = *reinterpret_cast<const unsigned long long*>(&g_biasp[g * 64 + 2 * p]);
        #pragma unroll
        for (int i = 0; i < 8; ++i)
            #pragma unroll
            for (int g = 0; g < 4; ++g) acc[i][g] = bini[g];
    }

    auto load_x = [&](int kc, float4& a, float4& b) {
        const float* sp; int ld, col;
        if (kc < 4)      { sp = x;   ld = IN_DIM; col = kc * KC; }
        else if (kc < 6) { sp = h;   ld = HID;    col = (kc - 4) * KC; }
        else if (kc < 8) { sp = tx1; ld = HID;    col = (kc - 6) * KC; }
        else             { sp = tx2; ld = HID;    col = (kc - 8) * KC; }
        if (gxn < N) {
            const float* base = sp + (long)gxn * ld + col;
            a = *reinterpret_cast<const float4*>(base + xq0 * 4);
            b = *reinterpret_cast<const float4*>(base + xq0 * 4 + 4);
        } else {
            a = make_float4(0.f, 0.f, 0.f, 0.f);
            b = a;
        }
    };
    auto store_x = [&](int buf, float4 a, float4 b) {
        float* X = buf ? Xs1 : Xs0;
        *reinterpret_cast<float4*>(&X[xn * KC + xq0 * 4])     = a;
        *reinterpret_cast<float4*>(&X[xn * KC + xq0 * 4 + 4]) = b;
    };
    auto issue_w = [&](int kc, int buf) {
        const float4* wp4 = reinterpret_cast<const float4*>(g_Wp + kc * KC * NCOLS);
        float4* ws4 = reinterpret_cast<float4*>(Wsb + buf * (KC * NCOLS));
        #pragma unroll
        for (int r = 0; r < 8; ++r)
            cp16(&ws4[tid + r * 256], &wp4[tid + r * 256]);
        CP_COMMIT();
    };

    issue_w(0, 0);
    {
        float4 a, b; load_x(0, a, b);
        store_x(0, a, b);
    }
    CP_WAIT0();
    __syncthreads();

    for (int kc = 0; kc < NCHUNK; ++kc) {
        const int cur = kc & 1;
        float4 xa, xb;
        if (kc < NCHUNK - 1) {
            if (kc == 7) {
                // chunk 8 (first tx2 chunk) is prefetched now — wait for k_agg<1>
                PDL_WAIT();
            }
            issue_w(kc + 1, cur ^ 1);
            load_x(kc + 1, xa, xb);
        }
        {
            const unsigned long long* wr =
                reinterpret_cast<const unsigned long long*>(Wsb + cur * (KC * NCOLS));
            const float* xf = cur ? Xs1 : Xs0;
            for (int ko = 0; ko < KC; ko += 8) {
                #pragma unroll
                for (int k8 = 0; k8 < 8; ++k8) {
                    int kk = ko + k8;
                    unsigned long long a[8], b[4];
                    #pragma unroll
                    for (int i = 0; i < 8; ++i) a[i] = dup2(xf[(ty + 8 * i) * KC + kk]);
                    #pragma unroll
                    for (int g = 0; g < 4; ++g) b[g] = wr[kk * 128 + g * 32 + p];
                    #pragma unroll
                    for (int i = 0; i < 8; ++i)
                        #pragma unroll
                        for (int g = 0; g < 4; ++g) acc[i][g] = ffma2(a[i], b[g], acc[i][g]);
                }
            }
        }
        if (kc < NCHUNK - 1)
            store_x(cur ^ 1, xa, xb);
        CP_WAIT0();
        __syncthreads();
    }

    // ---- phase 2: gates + h0/c0 + relu(h0)@Wl + bl (reuse smem) ----
    float* Hs  = sm;          // [64][64]
    float* Wls = sm + 4096;   // [64][64]

    #pragma unroll
    for (int i = 0; i < 8; ++i) {
        int nl = ty + 8 * i;
        int n = nb + nl;
        float2 pi = u2f(acc[i][0]);
        float2 pf = u2f(acc[i][1]);
        float2 pt = u2f(acc[i][2]);
        float2 po = u2f(acc[i][3]);
        float r0 = 0.0f, r1 = 0.0f;
        if (n < N) {
            float2 cold = *reinterpret_cast<const float2*>(c + (long)n * HID + 2 * p);
            float ig0 = sigf(pi.x), ig1 = sigf(pi.y);
            float fg0 = sigf(pf.x), fg1 = sigf(pf.y);
            float tg0 = tanhf(pt.x), tg1 = tanhf(pt.y);
            float og0 = sigf(po.x), og1 = sigf(po.y);
            float c00 = fg0 * cold.x + ig0 * tg0;
            float c01 = fg1 * cold.y + ig1 * tg1;
            float h00 = og0 * tanhf(c00);
            float h01 = og1 * tanhf(c01);
            *reinterpret_cast<float2*>(out + (long)N * HID + (long)n * HID + 2 * p)
                = make_float2(h00, h01);
            *reinterpret_cast<float2*>(out + 2L * N * HID + (long)n * HID + 2 * p)
                = make_float2(c00, c01);
            r0 = fmaxf(h00, 0.0f);
            r1 = fmaxf(h01, 0.0f);
        }
        Hs[nl * 64 + 2 * p]     = r0;
        Hs[nl * 64 + 2 * p + 1] = r1;
    }
    {
        float4* wl4 = reinterpret_cast<float4*>(Wls);
        const float4* wlg = reinterpret_cast<const float4*>(Wl);
        #pragma unroll
        for (int r = 0; r < 4; ++r) wl4[tid + r * 256] = wlg[tid + r * 256];
    }
    __syncthreads();

    float o0[8], o1[8];
    {
        float b0 = bl[2 * p], b1 = bl[2 * p + 1];
        #pragma unroll
        for (int i = 0; i < 8; ++i) { o0[i] = b0; o1[i] = b1; }
    }
    for (int k = 0; k < 64; ++k) {
        float2 w = *reinterpret_cast<const float2*>(Wls + k * 64 + 2 * p);
        #pragma unroll
        for (int i = 0; i < 8; ++i) {
            float a = Hs[(ty + 8 * i) * 64 + k];
            o0[i] = fmaf(a, w.x, o0[i]);
            o1[i] = fmaf(a, w.y, o1[i]);
        }
    }
    #pragma unroll
    for (int i = 0; i < 8; ++i) {
        int n = nb + ty + 8 * i;
        if (n < N)
            *reinterpret_cast<float2*>(out + (long)n * HID + 2 * p) = make_float2(o0[i], o1[i]);
    }
}

// ---------------- launch ----------------
static void launch_pdl(void* func, dim3 grid, dim3 block, size_t smem,
                       void** args) {
    cudaLaunchConfig_t cfg = {};
    cfg.gridDim  = grid;
    cfg.blockDim = block;
    cfg.dynamicSmemBytes = smem;
    cfg.stream = 0;
    cudaLaunchAttribute attr[1];
    attr[0].id = cudaLaunchAttributeProgrammaticStreamSerialization;
    attr[0].val.programmaticStreamSerializationAllowed = 1;
    cfg.attrs = attr;
    cfg.numAttrs = 1;
    cudaLaunchKernelExC(&cfg, func, args);
}

extern "C" void kernel_launch(void* const* d_in, const int* in_sizes, int n_in,
                              void* d_out, int out_size) {
    const float* x   = (const float*)d_in[0];
    const int*   ei  = (const int*)d_in[1];
    const float* ew  = (const float*)d_in[2];
    const float* h   = (const float*)d_in[3];
    const float* c   = (const float*)d_in[4];
    const float* Wx  = (const float*)d_in[5];
    const float* bg  = (const float*)d_in[6];
    const float* th  = (const float*)d_in[7];
    const float* cb  = (const float*)d_in[8];
    const float* Wl  = (const float*)d_in[9];
    const float* bl  = (const float*)d_in[10];
    float* out = (float*)d_out;

    const int N = in_sizes[0] / IN_DIM;
    const int E = in_sizes[1] / 2;
    const int* src = ei;
    const int* dst = ei + E;

    void *p_tx1v, *p_tx2v;
    cudaGetSymbolAddress(&p_tx1v, g_Tx1);
    cudaGetSymbolAddress(&p_tx2v, g_Tx2);
    const float* p_tx1 = (const float*)p_tx1v;
    const float* p_tx2 = (const float*)p_tx2v;

    static int smem_set = 0;
    if (!smem_set) {
        cudaFuncSetAttribute(k_fused, cudaFuncAttributeMaxDynamicSharedMemorySize,
                             SMEM_BYTES);
        smem_set = 1;
    }

    const int eb = (E + 255) / 256;
    const int pb = (KTOT * NCOLS + 255) / 256;
    const int nbk = (N + SCAN_BS - 1) / SCAN_BS;
    const int ab = (N * 16 + 255) / 256;

    k_zero<<<(N + 255) / 256, 256>>>(N);

    {
        void* args[] = {(void*)&src, (void*)&dst, (void*)&ew, (void*)&E, (void*)&eb,
                        (void*)&Wx, (void*)&bg, (void*)&th, (void*)&cb};
        launch_pdl((void*)k_preppack, dim3(eb + pb), dim3(256), 0, args);
    }
    {
        void* args[] = {(void*)&N};
        launch_pdl((void*)k_scan1, dim3(nbk), dim3(SCAN_BS), 0, args);
    }
    {
        void* args[] = {(void*)&nbk};
        launch_pdl((void*)k_scan2, dim3(1), dim3(MAX_SBLK), 0, args);
    }
    {
        void* args[] = {(void*)&src, (void*)&dst, (void*)&ew, (void*)&E};
        launch_pdl((void*)k_fill, dim3(eb), dim3(256), 0, args);
    }
    {
        const float4* z = (const float4*)h;
        const float4* hs = nullptr;
        float4* ob = (float4*)p_tx1v;
        void* args[] = {(void*)&z, (void*)&hs, (void*)&ob, (void*)&N};
        launch_pdl((void*)k_agg<0>, dim3(ab), dim3(256), 0, args);
    }
    {
        const float4* z = (const float4*)p_tx1v;
        const float4* hs = (const float4*)h;
        float4* ob = (float4*)p_tx2v;
        void* args[] = {(void*)&z, (void*)&hs, (void*)&ob, (void*)&N};
        launch_pdl((void*)k_agg<1>, dim3(ab), dim3(256), 0, args);
    }
    {
        void* args[] = {(void*)&x, (void*)&h, (void*)&p_tx1, (void*)&p_tx2,
                        (void*)&c, (void*)&Wl, (void*)&bl, (void*)&out, (void*)&N};
        launch_pdl((void*)k_fused, dim3((N + NPB - 1) / NPB), dim3(256),
                   SMEM_BYTES, args);
    }
}

// round 16
// speedup vs baseline: 1.5369x; 1.0081x over previous
#include <cuda_runtime.h>
#include <math.h>

#define NNODES_MAX 100000
#define NEDGES_MAX 1600000
#define IN_DIM 128
#define HID 64
#define KTOT 320   // IN_DIM + 3*HID
#define NCOLS 256  // 4 gates * HID
#define KC 32
#define NCHUNK 10  // KTOT / KC
#define NPB 64
#define SCAN_BS 256
#define MAX_SBLK 512
#define AGG_GRID 1184   // one resident wave: 152 SMs x ~8 CTAs (rounded for 148-152)
#define SMEM_BYTES (2 * (NPB * KC + KC * NCOLS) * 4)   // 81920

#define PDL_WAIT()    asm volatile("griddepcontrol.wait;" ::: "memory")
#define PDL_TRIGGER() asm volatile("griddepcontrol.launch_dependents;" ::: "memory")

// ---------------- scratch (static device globals; no allocation) ----------------
__device__ __align__(16) float g_deg [NNODES_MAX];
__device__ __align__(16) int   g_cnt [NNODES_MAX];
__device__ __align__(16) int   g_off [NNODES_MAX];   // block-LOCAL exclusive offset
__device__ __align__(16) int   g_cur [NNODES_MAX];   // ditto (fill adds block base)
__device__ __align__(16) int   g_bsum[MAX_SBLK];     // exclusive block bases
__device__ __align__(16) long long g_pay[NEDGES_MAX];   // {lw(f32)<<32 | src}
__device__ __align__(16) float g_Tx1 [NNODES_MAX * HID];
__device__ __align__(16) float g_Tx2 [NNODES_MAX * HID];
__device__ __align__(16) float g_Wp  [KTOT * NCOLS];
__device__ __align__(16) float g_biasp[NCOLS];

// ---------------- helpers ----------------
__device__ __forceinline__ float sigf(float v) { return 1.0f / (1.0f + expf(-v)); }

__device__ __forceinline__ unsigned long long ffma2(unsigned long long a,
                                                    unsigned long long b,
                                                    unsigned long long c) {
    unsigned long long d;
    asm("fma.rn.f32x2 %0, %1, %2, %3;" : "=l"(d) : "l"(a), "l"(b), "l"(c));
    return d;
}
__device__ __forceinline__ float2 u2f(unsigned long long u) {
    float2 f; asm("mov.b64 {%0,%1}, %2;" : "=f"(f.x), "=f"(f.y) : "l"(u)); return f;
}
__device__ __forceinline__ unsigned long long dup2(float v) {
    unsigned long long r; asm("mov.b64 %0, {%1, %1};" : "=l"(r) : "f"(v)); return r;
}
__device__ __forceinline__ void cp16(void* smem, const void* gmem) {
    unsigned sa = (unsigned)__cvta_generic_to_shared(smem);
    asm volatile("cp.async.cg.shared.global [%0], [%1], 16;" :: "r"(sa), "l"(gmem));
}
#define CP_COMMIT() asm volatile("cp.async.commit_group;" ::: "memory")
#define CP_WAIT0()  asm volatile("cp.async.wait_group 0;"  ::: "memory")

// ---------------- zero scratch + counters ----------------
__global__ void k_zero(int N) {
    PDL_TRIGGER();
    int i = blockIdx.x * blockDim.x + threadIdx.x;
    if (i < N) { g_deg[i] = 0.0f; g_cnt[i] = 0; }
}

// ---------------- prep (deg + hist) fused with weight pack, split by block ----------------
__global__ void k_preppack(const int* __restrict__ src, const int* __restrict__ dst,
                           const float* __restrict__ ew, int E, int eb,
                           const float* __restrict__ Wx, const float* __restrict__ bg,
                           const float* __restrict__ theta, const float* __restrict__ convb) {
    int b = blockIdx.x;
    if (b < eb) {
        PDL_WAIT();        // needs g_deg/g_cnt zeroed
        PDL_TRIGGER();
        int e = b * 256 + threadIdx.x;
        if (e >= E) return;
        int s = src[e], d = dst[e];
        float w = (s == d) ? 0.0f : ew[e];
        if (w != 0.0f) atomicAdd(&g_deg[s], w);
        atomicAdd(&g_cnt[d], 1);
    } else {
        PDL_TRIGGER();     // pack half independent of k_zero
        int idx = (b - eb) * 256 + threadIdx.x;
        if (idx >= KTOT * NCOLS) return;
        int k = idx / NCOLS, j = idx % NCOLS;
        int g = j >> 6, o = j & 63;
        float v;
        if (k < IN_DIM) {
            v = Wx[(g * IN_DIM + k) * HID + o];
        } else {
            int kk = k - IN_DIM;
            v = theta[((g * 3 + kk / HID) * HID + (kk % HID)) * HID + o];
        }
        g_Wp[idx] = v;
        if (idx < NCOLS) g_biasp[idx] = bg[idx] + convb[idx];
    }
}

// ---------------- scan: block-local exclusive offsets + block sums ----------------
__global__ void k_scan1(int N) {
    PDL_WAIT();            // needs g_cnt from preppack
    PDL_TRIGGER();
    __shared__ int sm[SCAN_BS];
    int t = threadIdx.x;
    int i = blockIdx.x * SCAN_BS + t;
    int v = (i < N) ? g_cnt[i] : 0;
    sm[t] = v; __syncthreads();
    #pragma unroll
    for (int d = 1; d < SCAN_BS; d <<= 1) {
        int u = (t >= d) ? sm[t - d] : 0;
        __syncthreads();
        sm[t] += u;
        __syncthreads();
    }
    if (i < N) { int o = sm[t] - v; g_off[i] = o; g_cur[i] = o; }
    if (t == SCAN_BS - 1) g_bsum[blockIdx.x] = sm[t];
}
__global__ void k_scan2(int nb) {
    PDL_WAIT();            // needs g_bsum from scan1
    PDL_TRIGGER();
    __shared__ int sm[MAX_SBLK];
    int t = threadIdx.x;
    int v = (t < nb) ? g_bsum[t] : 0;
    sm[t] = v; __syncthreads();
    #pragma unroll
    for (int d = 1; d < MAX_SBLK; d <<= 1) {
        int u = (t >= d) ? sm[t - d] : 0;
        __syncthreads();
        sm[t] += u;
        __syncthreads();
    }
    if (t < nb) g_bsum[t] = sm[t] - v;
}

// ---------------- fill CSR payload {src, lap_w} (adds block base on the fly) ----------------
__global__ void k_fill(const int* __restrict__ src, const int* __restrict__ dst,
                       const float* __restrict__ ew, int E) {
    PDL_WAIT();            // needs g_deg, g_cur, g_bsum
    PDL_TRIGGER();
    int e = blockIdx.x * blockDim.x + threadIdx.x;
    if (e >= E) return;
    int s = src[e], d = dst[e];
    float w  = (s == d) ? 0.0f : ew[e];
    float ds = g_deg[s], dd = g_deg[d];
    float is = (ds > 0.0f) ? rsqrtf(ds) : 0.0f;
    float id = (dd > 0.0f) ? rsqrtf(dd) : 0.0f;
    float lw = -is * w * id;
    int pos = atomicAdd(&g_cur[d], 1) + g_bsum[d >> 8];   // SCAN_BS = 256
    g_pay[pos] = ((long long)(unsigned long long)__float_as_uint(lw) << 32)
                 | (unsigned)s;
}

// ---------------- aggregate: one-wave persistent grid-stride; 16 threads/node ----------------
// Grid-stride so ALL CTAs are resident in wave 1 -> PDL_TRIGGER completes
// immediately and the dependent kernel overlaps this kernel's body.
template <int TX2>
__global__ __launch_bounds__(256) void k_agg(const float4* __restrict__ z,
                                             const float4* __restrict__ hsub,
                                             float4* __restrict__ outb,
                                             int N) {
    PDL_WAIT();            // needs g_pay (fill) resp. tx1 (agg<0>) COMPLETE
    PDL_TRIGGER();         // wave-1 trigger: releases the next kernel early
    const int W = N * 16;
    const int stride = gridDim.x * blockDim.x;
    for (int gid = blockIdx.x * blockDim.x + threadIdx.x; gid < W; gid += stride) {
        int n = gid >> 4;
        int c = gid & 15;
        int j   = g_off[n] + g_bsum[n >> 8];
        int end = j + g_cnt[n];

        float4 acc = make_float4(0.f, 0.f, 0.f, 0.f);
        for (; j + 7 < end; j += 8) {
            long long pp[8];
            #pragma unroll
            for (int u = 0; u < 8; ++u) pp[u] = g_pay[j + u];
            float4 vv[8];
            float  ll[8];
            #pragma unroll
            for (int u = 0; u < 8; ++u) {
                int s = (int)(pp[u] & 0xffffffffLL);
                ll[u] = __uint_as_float((unsigned)((unsigned long long)pp[u] >> 32));
                vv[u] = z[(long)s * 16 + c];
            }
            #pragma unroll
            for (int u = 0; u < 8; ++u) {
                acc.x = fmaf(ll[u], vv[u].x, acc.x);
                acc.y = fmaf(ll[u], vv[u].y, acc.y);
                acc.z = fmaf(ll[u], vv[u].z, acc.z);
                acc.w = fmaf(ll[u], vv[u].w, acc.w);
            }
        }
        for (; j < end; ++j) {
            long long p0 = g_pay[j];
            int   s0 = (int)(p0 & 0xffffffffLL);
            float l0 = __uint_as_float((unsigned)((unsigned long long)p0 >> 32));
            float4 v0 = z[(long)s0 * 16 + c];
            acc.x = fmaf(l0, v0.x, acc.x); acc.y = fmaf(l0, v0.y, acc.y);
            acc.z = fmaf(l0, v0.z, acc.z); acc.w = fmaf(l0, v0.w, acc.w);
        }
        if (TX2) {
            float4 hv = hsub[(long)n * 16 + c];
            acc.x = 2.0f * acc.x - hv.x; acc.y = 2.0f * acc.y - hv.y;
            acc.z = 2.0f * acc.z - hv.z; acc.w = 2.0f * acc.w - hv.w;
        }
        outb[(long)n * 16 + c] = acc;
    }
}

// ---------------- fused GEMM (320->256), KC=32 double-buffered, PDL-gated tx2 ----------------
__global__ __launch_bounds__(256, 2) void k_fused(
    const float* __restrict__ x, const float* __restrict__ h,
    const float* __restrict__ tx1, const float* __restrict__ tx2,
    const float* __restrict__ c, const float* __restrict__ Wl,
    const float* __restrict__ bl, float* __restrict__ out, int N) {

    extern __shared__ __align__(16) float sm[];
    float* Xs0 = sm;                 // 2048 floats
    float* Xs1 = sm + NPB * KC;      // 2048
    float* Wsb = sm + 2 * NPB * KC;  // 2 x 8192

    const int tid = threadIdx.x;
    const int p  = tid & 31;
    const int ty = tid >> 5;
    const int nb = blockIdx.x * NPB;
    const int xn  = tid >> 2;
    const int xq0 = (tid & 3) * 2;
    const int gxn = nb + xn;

    unsigned long long acc[8][4];
    {
        unsigned long long bini[4];
        #pragma unroll
        for (int g = 0; g < 4; ++g)
            bini[g] = *reinterpret_cast<const unsigned long long*>(&g_biasp[g * 64 + 2 * p]);
        #pragma unroll
        for (int i = 0; i < 8; ++i)
            #pragma unroll
            for (int g = 0; g < 4; ++g) acc[i][g] = bini[g];
    }

    auto load_x = [&](int kc, float4& a, float4& b) {
        const float* sp; int ld, col;
        if (kc < 4)      { sp = x;   ld = IN_DIM; col = kc * KC; }
        else if (kc < 6) { sp = h;   ld = HID;    col = (kc - 4) * KC; }
        else if (kc < 8) { sp = tx1; ld = HID;    col = (kc - 6) * KC; }
        else             { sp = tx2; ld = HID;    col = (kc - 8) * KC; }
        if (gxn < N) {
            const float* base = sp + (long)gxn * ld + col;
            a = *reinterpret_cast<const float4*>(base + xq0 * 4);
            b = *reinterpret_cast<const float4*>(base + xq0 * 4 + 4);
        } else {
            a = make_float4(0.f, 0.f, 0.f, 0.f);
            b = a;
        }
    };
    auto store_x = [&](int buf, float4 a, float4 b) {
        float* X = buf ? Xs1 : Xs0;
        *reinterpret_cast<float4*>(&X[xn * KC + xq0 * 4])     = a;
        *reinterpret_cast<float4*>(&X[xn * KC + xq0 * 4 + 4]) = b;
    };
    auto issue_w = [&](int kc, int buf) {
        const float4* wp4 = reinterpret_cast<const float4*>(g_Wp + kc * KC * NCOLS);
        float4* ws4 = reinterpret_cast<float4*>(Wsb + buf * (KC * NCOLS));
        #pragma unroll
        for (int r = 0; r < 8; ++r)
            cp16(&ws4[tid + r * 256], &wp4[tid + r * 256]);
        CP_COMMIT();
    };

    issue_w(0, 0);
    {
        float4 a, b; load_x(0, a, b);
        store_x(0, a, b);
    }
    CP_WAIT0();
    __syncthreads();

    for (int kc = 0; kc < NCHUNK; ++kc) {
        const int cur = kc & 1;
        float4 xa, xb;
        if (kc < NCHUNK - 1) {
            if (kc == 7) {
                // chunk 8 (first tx2 chunk) is prefetched now — wait for k_agg<1>
                PDL_WAIT();
            }
            issue_w(kc + 1, cur ^ 1);
            load_x(kc + 1, xa, xb);
        }
        {
            const unsigned long long* wr =
                reinterpret_cast<const unsigned long long*>(Wsb + cur * (KC * NCOLS));
            const float* xf = cur ? Xs1 : Xs0;
            for (int ko = 0; ko < KC; ko += 8) {
                #pragma unroll
                for (int k8 = 0; k8 < 8; ++k8) {
                    int kk = ko + k8;
                    unsigned long long a[8], b[4];
                    #pragma unroll
                    for (int i = 0; i < 8; ++i) a[i] = dup2(xf[(ty + 8 * i) * KC + kk]);
                    #pragma unroll
                    for (int g = 0; g < 4; ++g) b[g] = wr[kk * 128 + g * 32 + p];
                    #pragma unroll
                    for (int i = 0; i < 8; ++i)
                        #pragma unroll
                        for (int g = 0; g < 4; ++g) acc[i][g] = ffma2(a[i], b[g], acc[i][g]);
                }
            }
        }
        if (kc < NCHUNK - 1)
            store_x(cur ^ 1, xa, xb);
        CP_WAIT0();
        __syncthreads();
    }

    // ---- phase 2: gates + h0/c0 + relu(h0)@Wl + bl (reuse smem) ----
    float* Hs  = sm;          // [64][64]
    float* Wls = sm + 4096;   // [64][64]

    #pragma unroll
    for (int i = 0; i < 8; ++i) {
        int nl = ty + 8 * i;
        int n = nb + nl;
        float2 pi = u2f(acc[i][0]);
        float2 pf = u2f(acc[i][1]);
        float2 pt = u2f(acc[i][2]);
        float2 po = u2f(acc[i][3]);
        float r0 = 0.0f, r1 = 0.0f;
        if (n < N) {
            float2 cold = *reinterpret_cast<const float2*>(c + (long)n * HID + 2 * p);
            float ig0 = sigf(pi.x), ig1 = sigf(pi.y);
            float fg0 = sigf(pf.x), fg1 = sigf(pf.y);
            float tg0 = tanhf(pt.x), tg1 = tanhf(pt.y);
            float og0 = sigf(po.x), og1 = sigf(po.y);
            float c00 = fg0 * cold.x + ig0 * tg0;
            float c01 = fg1 * cold.y + ig1 * tg1;
            float h00 = og0 * tanhf(c00);
            float h01 = og1 * tanhf(c01);
            *reinterpret_cast<float2*>(out + (long)N * HID + (long)n * HID + 2 * p)
                = make_float2(h00, h01);
            *reinterpret_cast<float2*>(out + 2L * N * HID + (long)n * HID + 2 * p)
                = make_float2(c00, c01);
            r0 = fmaxf(h00, 0.0f);
            r1 = fmaxf(h01, 0.0f);
        }
        Hs[nl * 64 + 2 * p]     = r0;
        Hs[nl * 64 + 2 * p + 1] = r1;
    }
    {
        float4* wl4 = reinterpret_cast<float4*>(Wls);
        const float4* wlg = reinterpret_cast<const float4*>(Wl);
        #pragma unroll
        for (int r = 0; r < 4; ++r) wl4[tid + r * 256] = wlg[tid + r * 256];
    }
    __syncthreads();

    float o0[8], o1[8];
    {
        float b0 = bl[2 * p], b1 = bl[2 * p + 1];
        #pragma unroll
        for (int i = 0; i < 8; ++i) { o0[i] = b0; o1[i] = b1; }
    }
    for (int k = 0; k < 64; ++k) {
        float2 w = *reinterpret_cast<const float2*>(Wls + k * 64 + 2 * p);
        #pragma unroll
        for (int i = 0; i < 8; ++i) {
            float a = Hs[(ty + 8 * i) * 64 + k];
            o0[i] = fmaf(a, w.x, o0[i]);
            o1[i] = fmaf(a, w.y, o1[i]);
        }
    }
    #pragma unroll
    for (int i = 0; i < 8; ++i) {
        int n = nb + ty + 8 * i;
        if (n < N)
            *reinterpret_cast<float2*>(out + (long)n * HID + 2 * p) = make_float2(o0[i], o1[i]);
    }
}

// ---------------- launch ----------------
static void launch_pdl(void* func, dim3 grid, dim3 block, size_t smem,
                       void** args) {
    cudaLaunchConfig_t cfg = {};
    cfg.gridDim  = grid;
    cfg.blockDim = block;
    cfg.dynamicSmemBytes = smem;
    cfg.stream = 0;
    cudaLaunchAttribute attr[1];
    attr[0].id = cudaLaunchAttributeProgrammaticStreamSerialization;
    attr[0].val.programmaticStreamSerializationAllowed = 1;
    cfg.attrs = attr;
    cfg.numAttrs = 1;
    cudaLaunchKernelExC(&cfg, func, args);
}

extern "C" void kernel_launch(void* const* d_in, const int* in_sizes, int n_in,
                              void* d_out, int out_size) {
    const float* x   = (const float*)d_in[0];
    const int*   ei  = (const int*)d_in[1];
    const float* ew  = (const float*)d_in[2];
    const float* h   = (const float*)d_in[3];
    const float* c   = (const float*)d_in[4];
    const float* Wx  = (const float*)d_in[5];
    const float* bg  = (const float*)d_in[6];
    const float* th  = (const float*)d_in[7];
    const float* cb  = (const float*)d_in[8];
    const float* Wl  = (const float*)d_in[9];
    const float* bl  = (const float*)d_in[10];
    float* out = (float*)d_out;

    const int N = in_sizes[0] / IN_DIM;
    const int E = in_sizes[1] / 2;
    const int* src = ei;
    const int* dst = ei + E;

    void *p_tx1v, *p_tx2v;
    cudaGetSymbolAddress(&p_tx1v, g_Tx1);
    cudaGetSymbolAddress(&p_tx2v, g_Tx2);
    const float* p_tx1 = (const float*)p_tx1v;
    const float* p_tx2 = (const float*)p_tx2v;

    static int smem_set = 0;
    if (!smem_set) {
        cudaFuncSetAttribute(k_fused, cudaFuncAttributeMaxDynamicSharedMemorySize,
                             SMEM_BYTES);
        smem_set = 1;
    }

    const int eb = (E + 255) / 256;
    const int pb = (KTOT * NCOLS + 255) / 256;
    const int nbk = (N + SCAN_BS - 1) / SCAN_BS;
    int ab = (N * 16 + 255) / 256;
    if (ab > AGG_GRID) ab = AGG_GRID;   // one-wave persistent

    k_zero<<<(N + 255) / 256, 256>>>(N);

    {
        void* args[] = {(void*)&src, (void*)&dst, (void*)&ew, (void*)&E, (void*)&eb,
                        (void*)&Wx, (void*)&bg, (void*)&th, (void*)&cb};
        launch_pdl((void*)k_preppack, dim3(eb + pb), dim3(256), 0, args);
    }
    {
        void* args[] = {(void*)&N};
        launch_pdl((void*)k_scan1, dim3(nbk), dim3(SCAN_BS), 0, args);
    }
    {
        void* args[] = {(void*)&nbk};
        launch_pdl((void*)k_scan2, dim3(1), dim3(MAX_SBLK), 0, args);
    }
    {
        void* args[] = {(void*)&src, (void*)&dst, (void*)&ew, (void*)&E};
        launch_pdl((void*)k_fill, dim3(eb), dim3(256), 0, args);
    }
    {
        const float4* z = (const float4*)h;
        const float4* hs = nullptr;
        float4* ob = (float4*)p_tx1v;
        void* args[] = {(void*)&z, (void*)&hs, (void*)&ob, (void*)&N};
        launch_pdl((void*)k_agg<0>, dim3(ab), dim3(256), 0, args);
    }
    {
        const float4* z = (const float4*)p_tx1v;
        const float4* hs = (const float4*)h;
        float4* ob = (float4*)p_tx2v;
        void* args[] = {(void*)&z, (void*)&hs, (void*)&ob, (void*)&N};
        launch_pdl((void*)k_agg<1>, dim3(ab), dim3(256), 0, args);
    }
    {
        void* args[] = {(void*)&x, (void*)&h, (void*)&p_tx1, (void*)&p_tx2,
                        (void*)&c, (void*)&Wl, (void*)&bl, (void*)&out, (void*)&N};
        launch_pdl((void*)k_fused, dim3((N + NPB - 1) / NPB), dim3(256),
                   SMEM_BYTES, args);
    }
}

// round 17
// speedup vs baseline: 1.5465x; 1.0063x over previous
#include <cuda_runtime.h>
#include <math.h>

#define NNODES_MAX 100000
#define NEDGES_MAX 1600000
#define IN_DIM 128
#define HID 64
#define KTOT 320   // IN_DIM + 3*HID
#define NCOLS 256  // 4 gates * HID
#define KC 32
#define NCHUNK 10  // KTOT / KC
#define NPB 64
#define SCAN_BS 256
#define MAX_SBLK 512
#define AGG_GRID 1184   // one resident wave
#define SMEM_BYTES (2 * (NPB * KC + KC * NCOLS) * 4)   // 81920

#define PDL_WAIT()    asm volatile("griddepcontrol.wait;" ::: "memory")
#define PDL_TRIGGER() asm volatile("griddepcontrol.launch_dependents;" ::: "memory")

// ---------------- scratch (static device globals; no allocation) ----------------
__device__ __align__(16) float g_deg [NNODES_MAX];
__device__ __align__(16) int   g_cnt [NNODES_MAX];
__device__ __align__(16) int   g_off [NNODES_MAX];   // block-LOCAL exclusive offset
__device__ __align__(16) int   g_cur [NNODES_MAX];   // ditto (fill adds block base)
__device__ __align__(16) int   g_bsum[MAX_SBLK];     // exclusive block bases
__device__ __align__(16) long long g_pay[NEDGES_MAX];   // {lw(f32)<<32 | src}
__device__ __align__(16) float g_Tx1 [NNODES_MAX * HID];
__device__ __align__(16) float g_Tx2 [NNODES_MAX * HID];
__device__ __align__(16) float g_Wp  [KTOT * NCOLS];
__device__ __align__(16) float g_biasp[NCOLS];

// ---------------- helpers ----------------
__device__ __forceinline__ float sigf(float v) { return 1.0f / (1.0f + expf(-v)); }

__device__ __forceinline__ unsigned long long ffma2(unsigned long long a,
                                                    unsigned long long b,
                                                    unsigned long long c) {
    unsigned long long d;
    asm("fma.rn.f32x2 %0, %1, %2, %3;" : "=l"(d) : "l"(a), "l"(b), "l"(c));
    return d;
}
__device__ __forceinline__ float2 u2f(unsigned long long u) {
    float2 f; asm("mov.b64 {%0,%1}, %2;" : "=f"(f.x), "=f"(f.y) : "l"(u)); return f;
}
__device__ __forceinline__ unsigned long long dup2(float v) {
    unsigned long long r; asm("mov.b64 %0, {%1, %1};" : "=l"(r) : "f"(v)); return r;
}
__device__ __forceinline__ void cp16(void* smem, const void* gmem) {
    unsigned sa = (unsigned)__cvta_generic_to_shared(smem);
    asm volatile("cp.async.cg.shared.global [%0], [%1], 16;" :: "r"(sa), "l"(gmem));
}
#define CP_COMMIT() asm volatile("cp.async.commit_group;" ::: "memory")
#define CP_WAIT0()  asm volatile("cp.async.wait_group 0;"  ::: "memory")

// ---------------- zero scratch + counters ----------------
__global__ void k_zero(int N) {
    PDL_TRIGGER();
    int i = blockIdx.x * blockDim.x + threadIdx.x;
    if (i < N) { g_deg[i] = 0.0f; g_cnt[i] = 0; }
}

// ---------------- prep (deg + hist) fused with weight pack, split by block ----------------
__global__ void k_preppack(const int* __restrict__ src, const int* __restrict__ dst,
                           const float* __restrict__ ew, int E, int eb,
                           const float* __restrict__ Wx, const float* __restrict__ bg,
                           const float* __restrict__ theta, const float* __restrict__ convb) {
    int b = blockIdx.x;
    if (b < eb) {
        PDL_WAIT();        // needs g_deg/g_cnt zeroed
        PDL_TRIGGER();
        int e = b * 256 + threadIdx.x;
        if (e >= E) return;
        int s = src[e], d = dst[e];
        float w = (s == d) ? 0.0f : ew[e];
        if (w != 0.0f) atomicAdd(&g_deg[s], w);
        atomicAdd(&g_cnt[d], 1);
    } else {
        PDL_TRIGGER();     // pack half independent of k_zero
        int idx = (b - eb) * 256 + threadIdx.x;
        if (idx >= KTOT * NCOLS) return;
        int k = idx / NCOLS, j = idx % NCOLS;
        int g = j >> 6, o = j & 63;
        float v;
        if (k < IN_DIM) {
            v = Wx[(g * IN_DIM + k) * HID + o];
        } else {
            int kk = k - IN_DIM;
            v = theta[((g * 3 + kk / HID) * HID + (kk % HID)) * HID + o];
        }
        g_Wp[idx] = v;
        if (idx < NCOLS) g_biasp[idx] = bg[idx] + convb[idx];
    }
}

// ---------------- scan: block-local exclusive offsets + block sums ----------------
__global__ void k_scan1(int N) {
    PDL_WAIT();
    PDL_TRIGGER();
    __shared__ int sm[SCAN_BS];
    int t = threadIdx.x;
    int i = blockIdx.x * SCAN_BS + t;
    int v = (i < N) ? g_cnt[i] : 0;
    sm[t] = v; __syncthreads();
    #pragma unroll
    for (int d = 1; d < SCAN_BS; d <<= 1) {
        int u = (t >= d) ? sm[t - d] : 0;
        __syncthreads();
        sm[t] += u;
        __syncthreads();
    }
    if (i < N) { int o = sm[t] - v; g_off[i] = o; g_cur[i] = o; }
    if (t == SCAN_BS - 1) g_bsum[blockIdx.x] = sm[t];
}
__global__ void k_scan2(int nb) {
    PDL_WAIT();
    PDL_TRIGGER();
    __shared__ int sm[MAX_SBLK];
    int t = threadIdx.x;
    int v = (t < nb) ? g_bsum[t] : 0;
    sm[t] = v; __syncthreads();
    #pragma unroll
    for (int d = 1; d < MAX_SBLK; d <<= 1) {
        int u = (t >= d) ? sm[t - d] : 0;
        __syncthreads();
        sm[t] += u;
        __syncthreads();
    }
    if (t < nb) g_bsum[t] = sm[t] - v;
}

// ---------------- fill CSR payload {src, lap_w} (adds block base on the fly) ----------------
__global__ void k_fill(const int* __restrict__ src, const int* __restrict__ dst,
                       const float* __restrict__ ew, int E) {
    PDL_WAIT();
    PDL_TRIGGER();
    int e = blockIdx.x * blockDim.x + threadIdx.x;
    if (e >= E) return;
    int s = src[e], d = dst[e];
    float w  = (s == d) ? 0.0f : ew[e];
    float ds = g_deg[s], dd = g_deg[d];
    float is = (ds > 0.0f) ? rsqrtf(ds) : 0.0f;
    float id = (dd > 0.0f) ? rsqrtf(dd) : 0.0f;
    float lw = -is * w * id;
    int pos = atomicAdd(&g_cur[d], 1) + g_bsum[d >> 8];   // SCAN_BS = 256
    g_pay[pos] = ((long long)(unsigned long long)__float_as_uint(lw) << 32)
                 | (unsigned)s;
}

// ---------------- aggregate: one-wave persistent grid-stride; 16 threads/node ----------------
template <int TX2>
__global__ __launch_bounds__(256) void k_agg(const float4* __restrict__ z,
                                             const float4* __restrict__ hsub,
                                             float4* __restrict__ outb,
                                             int N) {
    PDL_WAIT();            // needs g_pay (fill) resp. tx1 (agg<0>) COMPLETE
    PDL_TRIGGER();         // wave-1 trigger: releases the next kernel early
    const int W = N * 16;
    const int stride = gridDim.x * blockDim.x;
    for (int gid = blockIdx.x * blockDim.x + threadIdx.x; gid < W; gid += stride) {
        int n = gid >> 4;
        int c = gid & 15;
        int j   = g_off[n] + g_bsum[n >> 8];
        int end = j + g_cnt[n];

        float4 acc = make_float4(0.f, 0.f, 0.f, 0.f);
        for (; j + 7 < end; j += 8) {
            long long pp[8];
            #pragma unroll
            for (int u = 0; u < 8; ++u) pp[u] = g_pay[j + u];
            float4 vv[8];
            float  ll[8];
            #pragma unroll
            for (int u = 0; u < 8; ++u) {
                int s = (int)(pp[u] & 0xffffffffLL);
                ll[u] = __uint_as_float((unsigned)((unsigned long long)pp[u] >> 32));
                vv[u] = z[(long)s * 16 + c];
            }
            #pragma unroll
            for (int u = 0; u < 8; ++u) {
                acc.x = fmaf(ll[u], vv[u].x, acc.x);
                acc.y = fmaf(ll[u], vv[u].y, acc.y);
                acc.z = fmaf(ll[u], vv[u].z, acc.z);
                acc.w = fmaf(ll[u], vv[u].w, acc.w);
            }
        }
        for (; j < end; ++j) {
            long long p0 = g_pay[j];
            int   s0 = (int)(p0 & 0xffffffffLL);
            float l0 = __uint_as_float((unsigned)((unsigned long long)p0 >> 32));
            float4 v0 = z[(long)s0 * 16 + c];
            acc.x = fmaf(l0, v0.x, acc.x); acc.y = fmaf(l0, v0.y, acc.y);
            acc.z = fmaf(l0, v0.z, acc.z); acc.w = fmaf(l0, v0.w, acc.w);
        }
        if (TX2) {
            float4 hv = hsub[(long)n * 16 + c];
            acc.x = 2.0f * acc.x - hv.x; acc.y = 2.0f * acc.y - hv.y;
            acc.z = 2.0f * acc.z - hv.z; acc.w = 2.0f * acc.w - hv.w;
        }
        outb[(long)n * 16 + c] = acc;
    }
}

// ---------------- fused GEMM (320->256), KC=32 double-buffered, PDL-gated tx2 ----------------
__global__ __launch_bounds__(256, 2) void k_fused(
    const float* __restrict__ x, const float* __restrict__ h,
    const float* __restrict__ tx1, const float* __restrict__ tx2,
    const float* __restrict__ c, const float* __restrict__ Wl,
    const float* __restrict__ bl, float* __restrict__ out, int N) {

    extern __shared__ __align__(16) float sm[];
    float* Xs0 = sm;                 // 2048 floats
    float* Xs1 = sm + NPB * KC;      // 2048
    float* Wsb = sm + 2 * NPB * KC;  // 2 x 8192

    const int tid = threadIdx.x;
    const int p  = tid & 31;
    const int ty = tid >> 5;
    const int nb = blockIdx.x * NPB;
    const int xn  = tid >> 2;
    const int xq0 = (tid & 3) * 2;
    const int gxn = nb + xn;

    unsigned long long acc[8][4];
    {
        unsigned long long bini[4];
        #pragma unroll
        for (int g = 0; g < 4; ++g)
            bini[g] = *reinterpret_cast<const unsigned long long*>(&g_biasp[g * 64 + 2 * p]);
        #pragma unroll
        for (int i = 0; i < 8; ++i)
            #pragma unroll
            for (int g = 0; g < 4; ++g) acc[i][g] = bini[g];
    }

    auto load_x = [&](int kc, float4& a, float4& b) {
        const float* sp; int ld, col;
        if (kc < 4)      { sp = x;   ld = IN_DIM; col = kc * KC; }
        else if (kc < 6) { sp = h;   ld = HID;    col = (kc - 4) * KC; }
        else if (kc < 8) { sp = tx1; ld = HID;    col = (kc - 6) * KC; }
        else             { sp = tx2; ld = HID;    col = (kc - 8) * KC; }
        if (gxn < N) {
            const float* base = sp + (long)gxn * ld + col;
            a = *reinterpret_cast<const float4*>(base + xq0 * 4);
            b = *reinterpret_cast<const float4*>(base + xq0 * 4 + 4);
        } else {
            a = make_float4(0.f, 0.f, 0.f, 0.f);
            b = a;
        }
    };
    auto store_x = [&](int buf, float4 a, float4 b) {
        float* X = buf ? Xs1 : Xs0;
        *reinterpret_cast<float4*>(&X[xn * KC + xq0 * 4])     = a;
        *reinterpret_cast<float4*>(&X[xn * KC + xq0 * 4 + 4]) = b;
    };
    auto issue_w = [&](int kc, int buf) {
        const float4* wp4 = reinterpret_cast<const float4*>(g_Wp + kc * KC * NCOLS);
        float4* ws4 = reinterpret_cast<float4*>(Wsb + buf * (KC * NCOLS));
        #pragma unroll
        for (int r = 0; r < 8; ++r)
            cp16(&ws4[tid + r * 256], &wp4[tid + r * 256]);
        CP_COMMIT();
    };

    issue_w(0, 0);
    {
        float4 a, b; load_x(0, a, b);
        store_x(0, a, b);
    }
    CP_WAIT0();
    __syncthreads();

    for (int kc = 0; kc < NCHUNK; ++kc) {
        const int cur = kc & 1;
        float4 xa, xb;
        if (kc < NCHUNK - 1) {
            if (kc == 7) {
                // chunk 8 (first tx2 chunk) is prefetched now — wait for k_agg<1>
                PDL_WAIT();
            }
            issue_w(kc + 1, cur ^ 1);
            load_x(kc + 1, xa, xb);
        }
        {
            const unsigned long long* wr =
                reinterpret_cast<const unsigned long long*>(Wsb + cur * (KC * NCOLS));
            const float* xf = cur ? Xs1 : Xs0;
            for (int ko = 0; ko < KC; ko += 8) {
                #pragma unroll
                for (int k8 = 0; k8 < 8; ++k8) {
                    int kk = ko + k8;
                    unsigned long long a[8], b[4];
                    #pragma unroll
                    for (int i = 0; i < 8; ++i) a[i] = dup2(xf[(ty + 8 * i) * KC + kk]);
                    #pragma unroll
                    for (int g = 0; g < 4; ++g) b[g] = wr[kk * 128 + g * 32 + p];
                    #pragma unroll
                    for (int i = 0; i < 8; ++i)
                        #pragma unroll
                        for (int g = 0; g < 4; ++g) acc[i][g] = ffma2(a[i], b[g], acc[i][g]);
                }
            }
        }
        if (kc < NCHUNK - 1)
            store_x(cur ^ 1, xa, xb);
        CP_WAIT0();
        __syncthreads();
    }

    // ---- phase 2: gates + h0/c0 + relu(h0)@Wl + bl (reuse smem) ----
    float* Hs  = sm;          // [64][64]
    float* Wls = sm + 4096;   // [64][64]

    // stage Wl via cp.async NOW so the load flies under the MUFU-heavy gate math
    {
        float4* wl4 = reinterpret_cast<float4*>(Wls);
        const float4* wlg = reinterpret_cast<const float4*>(Wl);
        #pragma unroll
        for (int r = 0; r < 4; ++r)
            cp16(&wl4[tid + r * 256], &wlg[tid + r * 256]);
        CP_COMMIT();
    }

    #pragma unroll
    for (int i = 0; i < 8; ++i) {
        int nl = ty + 8 * i;
        int n = nb + nl;
        float2 pi = u2f(acc[i][0]);
        float2 pf = u2f(acc[i][1]);
        float2 pt = u2f(acc[i][2]);
        float2 po = u2f(acc[i][3]);
        float r0 = 0.0f, r1 = 0.0f;
        if (n < N) {
            float2 cold = *reinterpret_cast<const float2*>(c + (long)n * HID + 2 * p);
            float ig0 = sigf(pi.x), ig1 = sigf(pi.y);
            float fg0 = sigf(pf.x), fg1 = sigf(pf.y);
            float tg0 = tanhf(pt.x), tg1 = tanhf(pt.y);
            float og0 = sigf(po.x), og1 = sigf(po.y);
            float c00 = fg0 * cold.x + ig0 * tg0;
            float c01 = fg1 * cold.y + ig1 * tg1;
            float h00 = og0 * tanhf(c00);
            float h01 = og1 * tanhf(c01);
            *reinterpret_cast<float2*>(out + (long)N * HID + (long)n * HID + 2 * p)
                = make_float2(h00, h01);
            *reinterpret_cast<float2*>(out + 2L * N * HID + (long)n * HID + 2 * p)
                = make_float2(c00, c01);
            r0 = fmaxf(h00, 0.0f);
            r1 = fmaxf(h01, 0.0f);
        }
        Hs[nl * 64 + 2 * p]     = r0;
        Hs[nl * 64 + 2 * p + 1] = r1;
    }
    CP_WAIT0();
    __syncthreads();

    // ---- f32x2 mini-GEMM: out = relu(h0) @ Wl + bl ----
    unsigned long long o2[8];
    {
        unsigned long long blv = *reinterpret_cast<const unsigned long long*>(bl + 2 * p);
        #pragma unroll
        for (int i = 0; i < 8; ++i) o2[i] = blv;
    }
    const unsigned long long* Wl2 = reinterpret_cast<const unsigned long long*>(Wls);
    for (int k = 0; k < 64; ++k) {
        unsigned long long w = Wl2[k * 32 + p];
        #pragma unroll
        for (int i = 0; i < 8; ++i)
            o2[i] = ffma2(dup2(Hs[(ty + 8 * i) * 64 + k]), w, o2[i]);
    }
    #pragma unroll
    for (int i = 0; i < 8; ++i) {
        int n = nb + ty + 8 * i;
        if (n < N) {
            float2 v = u2f(o2[i]);
            *reinterpret_cast<float2*>(out + (long)n * HID + 2 * p) = v;
        }
    }
}

// ---------------- launch ----------------
static void launch_pdl(void* func, dim3 grid, dim3 block, size_t smem,
                       void** args) {
    cudaLaunchConfig_t cfg = {};
    cfg.gridDim  = grid;
    cfg.blockDim = block;
    cfg.dynamicSmemBytes = smem;
    cfg.stream = 0;
    cudaLaunchAttribute attr[1];
    attr[0].id = cudaLaunchAttributeProgrammaticStreamSerialization;
    attr[0].val.programmaticStreamSerializationAllowed = 1;
    cfg.attrs = attr;
    cfg.numAttrs = 1;
    cudaLaunchKernelExC(&cfg, func, args);
}

extern "C" void kernel_launch(void* const* d_in, const int* in_sizes, int n_in,
                              void* d_out, int out_size) {
    const float* x   = (const float*)d_in[0];
    const int*   ei  = (const int*)d_in[1];
    const float* ew  = (const float*)d_in[2];
    const float* h   = (const float*)d_in[3];
    const float* c   = (const float*)d_in[4];
    const float* Wx  = (const float*)d_in[5];
    const float* bg  = (const float*)d_in[6];
    const float* th  = (const float*)d_in[7];
    const float* cb  = (const float*)d_in[8];
    const float* Wl  = (const float*)d_in[9];
    const float* bl  = (const float*)d_in[10];
    float* out = (float*)d_out;

    const int N = in_sizes[0] / IN_DIM;
    const int E = in_sizes[1] / 2;
    const int* src = ei;
    const int* dst = ei + E;

    void *p_tx1v, *p_tx2v;
    cudaGetSymbolAddress(&p_tx1v, g_Tx1);
    cudaGetSymbolAddress(&p_tx2v, g_Tx2);
    const float* p_tx1 = (const float*)p_tx1v;
    const float* p_tx2 = (const float*)p_tx2v;

    static int smem_set = 0;
    if (!smem_set) {
        cudaFuncSetAttribute(k_fused, cudaFuncAttributeMaxDynamicSharedMemorySize,
                             SMEM_BYTES);
        smem_set = 1;
    }

    const int eb = (E + 255) / 256;
    const int pb = (KTOT * NCOLS + 255) / 256;
    const int nbk = (N + SCAN_BS - 1) / SCAN_BS;
    int ab = (N * 16 + 255) / 256;
    if (ab > AGG_GRID) ab = AGG_GRID;   // one-wave persistent

    k_zero<<<(N + 255) / 256, 256>>>(N);

    {
        void* args[] = {(void*)&src, (void*)&dst, (void*)&ew, (void*)&E, (void*)&eb,
                        (void*)&Wx, (void*)&bg, (void*)&th, (void*)&cb};
        launch_pdl((void*)k_preppack, dim3(eb + pb), dim3(256), 0, args);
    }
    {
        void* args[] = {(void*)&N};
        launch_pdl((void*)k_scan1, dim3(nbk), dim3(SCAN_BS), 0, args);
    }
    {
        void* args[] = {(void*)&nbk};
        launch_pdl((void*)k_scan2, dim3(1), dim3(MAX_SBLK), 0, args);
    }
    {
        void* args[] = {(void*)&src, (void*)&dst, (void*)&ew, (void*)&E};
        launch_pdl((void*)k_fill, dim3(eb), dim3(256), 0, args);
    }
    {
        const float4* z = (const float4*)h;
        const float4* hs = nullptr;
        float4* ob = (float4*)p_tx1v;
        void* args[] = {(void*)&z, (void*)&hs, (void*)&ob, (void*)&N};
        launch_pdl((void*)k_agg<0>, dim3(ab), dim3(256), 0, args);
    }
    {
        const float4* z = (const float4*)p_tx1v;
        const float4* hs = (const float4*)h;
        float4* ob = (float4*)p_tx2v;
        void* args[] = {(void*)&z, (void*)&hs, (void*)&ob, (void*)&N};
        launch_pdl((void*)k_agg<1>, dim3(ab), dim3(256), 0, args);
    }
    {
        void* args[] = {(void*)&x, (void*)&h, (void*)&p_tx1, (void*)&p_tx2,
                        (void*)&c, (void*)&Wl, (void*)&bl, (void*)&out, (void*)&N};
        launch_pdl((void*)k_fused, dim3((N + NPB - 1) / NPB), dim3(256),
                   SMEM_BYTES, args);
    }
}